// round 6
// baseline (speedup 1.0000x reference)
#include <cuda_runtime.h>
#include <cstdint>

#define TOK 4096
#define QKV_ELEMS ((size_t)TOK * 6144)

// ---- scratch ----
__device__ float g_comp[TOK * 8];
__device__ float g_q[QKV_ELEMS];
__device__ float g_k[QKV_ELEMS];
__device__ float g_v[QKV_ELEMS];
__device__ float g_o[QKV_ELEMS];
// tf32-pre-rounded operands
__device__ float g_xr[4194304];
__device__ float g_wqr[786432];
__device__ float g_wkr[786432];
__device__ float g_wvr[786432];
__device__ float g_wfr[786432];

// ============================================================
// helpers
// ============================================================
__device__ __forceinline__ uint32_t smem_u32(const void* p) {
    uint32_t a;
    asm("{ .reg .u64 t; cvta.to.shared.u64 t, %1; cvt.u32.u64 %0, t; }"
        : "=r"(a) : "l"(p));
    return a;
}
__device__ __forceinline__ uint32_t tf32r(float x) {
    uint32_t u;
    asm("cvt.rna.tf32.f32 %0, %1;" : "=r"(u) : "f"(x));
    return u;
}
__device__ __forceinline__ void cp16(uint32_t dst, const void* src) {
    asm volatile("cp.async.ca.shared.global [%0], [%1], 16;"
                 :: "r"(dst), "l"(src));
}
#define CP_COMMIT() asm volatile("cp.async.commit_group;" ::: "memory")
#define CP_WAIT(n)  asm volatile("cp.async.wait_group %0;" :: "n"(n) : "memory")

__device__ __forceinline__ void mma_tf32(float* c, const uint32_t* a,
                                         const uint32_t* b) {
    asm volatile(
        "mma.sync.aligned.m16n8k8.row.col.f32.tf32.tf32.f32 "
        "{%0,%1,%2,%3}, {%4,%5,%6,%7}, {%8,%9}, {%0,%1,%2,%3};"
        : "+f"(c[0]), "+f"(c[1]), "+f"(c[2]), "+f"(c[3])
        : "r"(a[0]), "r"(a[1]), "r"(a[2]), "r"(a[3]), "r"(b[0]), "r"(b[1]));
}

// ============================================================
// merged tf32 pre-round pass: x + 4 weight tensors, one launch
// ============================================================
#define X4   1048576          // x float4 count
#define W4   196608           // each weight float4 count
#define TOT4 (X4 + 4 * W4)    // 1835008

__global__ void round_all(const float* __restrict__ x,
                          const float* __restrict__ wq,
                          const float* __restrict__ wk,
                          const float* __restrict__ wv,
                          const float* __restrict__ wf,
                          float* __restrict__ xo, float* __restrict__ qo,
                          float* __restrict__ ko, float* __restrict__ vo,
                          float* __restrict__ fo) {
    int i = blockIdx.x * blockDim.x + threadIdx.x;
    if (i >= TOT4) return;
    const float4* src;
    float4* dst;
    int j = i;
    if (j < X4)                { src = (const float4*)x;  dst = (float4*)xo; }
    else if ((j -= X4) < W4)   { src = (const float4*)wq; dst = (float4*)qo; }
    else if ((j -= W4) < W4)   { src = (const float4*)wk; dst = (float4*)ko; }
    else if ((j -= W4) < W4)   { src = (const float4*)wv; dst = (float4*)vo; }
    else { j -= W4;              src = (const float4*)wf; dst = (float4*)fo; }
    float4 v = src[j];
    v.x = __uint_as_float(tf32r(v.x));
    v.y = __uint_as_float(tf32r(v.y));
    v.z = __uint_as_float(tf32r(v.z));
    v.w = __uint_as_float(tf32r(v.w));
    dst[j] = v;
}

// ============================================================
// Kernel A: competition gating
// ============================================================
__global__ void comp_kernel(const float* __restrict__ x,
                            const float* __restrict__ wc) {
    int gtid = blockIdx.x * blockDim.x + threadIdx.x;
    int t    = gtid >> 5;
    int lane = gtid & 31;
    if (t >= TOK) return;
    const float* xr = x + (size_t)t * 1024;

    float logit[8];
#pragma unroll
    for (int n = 0; n < 8; n++) {
        const float* xb = xr + n * 128;
        const float* wb = wc + n * 128;
        float p = xb[lane]      * wb[lane]
                + xb[lane + 32] * wb[lane + 32]
                + xb[lane + 64] * wb[lane + 64]
                + xb[lane + 96] * wb[lane + 96];
#pragma unroll
        for (int o = 16; o > 0; o >>= 1) p += __shfl_xor_sync(0xffffffffu, p, o);
        logit[n] = p;
    }
    float mx = logit[0];
#pragma unroll
    for (int n = 1; n < 8; n++) mx = fmaxf(mx, logit[n]);
    float s = 0.f, ev = 0.f;
#pragma unroll
    for (int n = 0; n < 8; n++) {
        float e = __expf(logit[n] - mx);
        s += e;
        if (lane == n) ev = e;
    }
    if (lane < 8) g_comp[t * 8 + lane] = ev / s;
}

// ============================================================
// tf32 mma.sync block-GEMM, templated tile.
//   MT x NT CTA tile, NTHR threads, 3-stage cp.async, k-chunk 32.
//   Operands pre-rounded tf32 in gmem. Warp grid (MT/32) x rest,
//   warp tile 32 x (NT/NWN).
// ============================================================
#define AS_STRIDE 36

template<int MT, int NT, int NTHR>
__global__ __launch_bounds__(NTHR, NTHR == 256 ? 2 : 1)
void gemm_mma(const float* __restrict__ Abase, int lda, int a_blk,
              const float* __restrict__ W0, const float* __restrict__ W1,
              const float* __restrict__ W2, int ldb, int w_blk, int TPM,
              float* __restrict__ C0, float* __restrict__ C1,
              float* __restrict__ C2, int ldc, int c_blk,
              int KC, const float* __restrict__ comp) {
    constexpr int BSS   = NT + 8;           // B smem stride (== 8 mod 32)
    constexpr int A_BUF = MT * AS_STRIDE;
    constexpr int B_BUF = 32 * BSS;
    constexpr int STG   = A_BUF + B_BUF;
    constexpr int NWM   = MT / 32;
    constexpr int NWN   = (NTHR / 32) / NWM;
    constexpr int WNW   = NT / NWN;
    constexpr int JN    = WNW / 8;

    extern __shared__ __align__(16) float sm[];
    const uint32_t sbase = smem_u32(sm);

    const int tid  = threadIdx.x;
    const int wid  = tid >> 5;
    const int lane = tid & 31;
    const int wm   = wid % NWM;
    const int wn   = wid / NWM;
    const int g    = lane >> 2;
    const int t    = lane & 3;

    const int mt   = blockIdx.x;
    const int yy   = blockIdx.y;
    const int zb   = blockIdx.z;
    const int mat  = yy / TPM;
    const int col0 = (yy % TPM) * NT;

    const float* W = (mat == 0 ? W0 : (mat == 1 ? W1 : W2)) +
                     (size_t)zb * w_blk + col0;
    float* C = (mat == 0 ? C0 : (mat == 1 ? C1 : C2)) +
               (size_t)zb * c_blk + col0;
    const float* A = Abase + (size_t)mt * MT * lda + (size_t)zb * a_blk;

    const int a_m  = tid >> 3;          // + p*(NTHR/8)
    const int a_k4 = tid & 7;

    float acc[2][JN][4];
#pragma unroll
    for (int i = 0; i < 2; i++)
#pragma unroll
        for (int j = 0; j < JN; j++)
#pragma unroll
            for (int c = 0; c < 4; c++) acc[i][j][c] = 0.f;

    auto issue_chunk = [&](int kc) {
        const int st = kc % 3;
        const uint32_t ad = sbase + (uint32_t)(st * STG) * 4;
        const uint32_t bd = ad + (uint32_t)A_BUF * 4;
        const int k0 = kc * 32;
#pragma unroll
        for (int p = 0; p < MT * 8 / NTHR; p++) {
            int m = a_m + p * (NTHR / 8);
            cp16(ad + (uint32_t)(m * AS_STRIDE + a_k4 * 4) * 4,
                 A + (size_t)m * lda + k0 + a_k4 * 4);
        }
#pragma unroll
        for (int p = 0; p < 32 * (NT / 4) / NTHR; p++) {
            int idx = p * NTHR + tid;
            int k   = idx / (NT / 4);
            int e4  = idx % (NT / 4);
            cp16(bd + (uint32_t)(k * BSS + e4 * 4) * 4,
                 W + (size_t)(k0 + k) * ldb + e4 * 4);
        }
    };

    // prologue: 2 chunks in flight
    issue_chunk(0);
    CP_COMMIT();
    if (KC > 1) { issue_chunk(1); CP_COMMIT(); }

    for (int kc = 0; kc < KC; kc++) {
        if (kc + 1 < KC) { CP_WAIT(1); } else { CP_WAIT(0); }
        __syncthreads();
        if (kc + 2 < KC) { issue_chunk(kc + 2); CP_COMMIT(); }

        const float* as = sm + (kc % 3) * STG;
        const float* bs = as + A_BUF;
#pragma unroll
        for (int ks = 0; ks < 4; ks++) {
            const int kk = ks * 8;
            uint32_t af[2][4];
#pragma unroll
            for (int i = 0; i < 2; i++) {
                const int r0 = wm * 32 + i * 16;
                af[i][0] = __float_as_uint(as[(r0 + g)     * AS_STRIDE + kk + t]);
                af[i][1] = __float_as_uint(as[(r0 + g + 8) * AS_STRIDE + kk + t]);
                af[i][2] = __float_as_uint(as[(r0 + g)     * AS_STRIDE + kk + t + 4]);
                af[i][3] = __float_as_uint(as[(r0 + g + 8) * AS_STRIDE + kk + t + 4]);
            }
            uint32_t bf[JN][2];
#pragma unroll
            for (int j = 0; j < JN; j++) {
                const int c = wn * WNW + j * 8 + g;
                bf[j][0] = __float_as_uint(bs[(kk + t)     * BSS + c]);
                bf[j][1] = __float_as_uint(bs[(kk + t + 4) * BSS + c]);
            }
#pragma unroll
            for (int i = 0; i < 2; i++)
#pragma unroll
                for (int j = 0; j < JN; j++)
                    mma_tf32(acc[i][j], af[i], bf[j]);
        }
    }

    // ---- epilogue ----
#pragma unroll
    for (int i = 0; i < 2; i++) {
        const int r0 = mt * MT + wm * 32 + i * 16 + g;
        const int r1 = r0 + 8;
        float sc0 = 1.f, sc1 = 1.f;
        if (comp) { sc0 = comp[r0 * 8 + zb]; sc1 = comp[r1 * 8 + zb]; }
        float* Cr0 = C + (size_t)r0 * ldc;
        float* Cr1 = C + (size_t)r1 * ldc;
#pragma unroll
        for (int j = 0; j < JN; j++) {
            const int c = wn * WNW + j * 8 + 2 * t;
            float2 v0 = make_float2(acc[i][j][0] * sc0, acc[i][j][1] * sc0);
            float2 v1 = make_float2(acc[i][j][2] * sc1, acc[i][j][3] * sc1);
            *(float2*)(Cr0 + c) = v0;
            *(float2*)(Cr1 + c) = v1;
        }
    }
}

// ============================================================
// Kernel C: block-attention per token; stores g_o tf32-rounded
// ============================================================
#define SMEM_ATTN ((12*8*65 + 12*8*65 + 12*8*64 + 12*64) * 4)

__global__ void attn_kernel(float* __restrict__ out) {
    extern __shared__ float smf[];
    float* sq = smf;
    float* sk = sq + 6240;
    float* sv = sk + 6240;
    float* ss = sv + 6144;

    const int t   = blockIdx.x;
    const int tid = threadIdx.x;
    const size_t base = (size_t)t * 6144;

#pragma unroll
    for (int it = 0; it < 16; it++) {
        int idx = it * 384 + tid;
        int nn  = idx / 768;
        int r   = idx - nn * 768;
        int h   = r >> 6;
        int j   = r & 63;
        sq[h * 520 + nn * 65 + j] = g_q[base + idx] * 0.125f;
        sk[h * 520 + nn * 65 + j] = g_k[base + idx];
        sv[h * 512 + nn * 64 + j] = g_v[base + idx];
    }
    __syncthreads();

    const int w    = tid >> 5;
    const int lane = tid & 31;
    float* q = sq + w * 520;
    float* k = sk + w * 520;
    float* v = sv + w * 512;
    float* s = ss + w * 64;

    const int nr = lane >> 3;
    const int mc = lane & 7;

    float s0 = 0.f, s1 = 0.f;
#pragma unroll
    for (int j = 0; j < 64; j++) {
        float kv = k[mc * 65 + j];
        s0 = fmaf(q[nr * 65 + j], kv, s0);
        s1 = fmaf(q[(nr + 4) * 65 + j], kv, s1);
    }
    float m0 = s0, m1 = s1;
#pragma unroll
    for (int o = 1; o < 8; o <<= 1) {
        m0 = fmaxf(m0, __shfl_xor_sync(0xffffffffu, m0, o));
        m1 = fmaxf(m1, __shfl_xor_sync(0xffffffffu, m1, o));
    }
    float e0 = __expf(s0 - m0), e1 = __expf(s1 - m1);
    float d0 = e0, d1 = e1;
#pragma unroll
    for (int o = 1; o < 8; o <<= 1) {
        d0 += __shfl_xor_sync(0xffffffffu, d0, o);
        d1 += __shfl_xor_sync(0xffffffffu, d1, o);
    }
    float a0 = e0 / d0, a1 = e1 / d1;
    s[nr * 8 + mc]       = a0;
    s[(nr + 4) * 8 + mc] = a1;
    __syncwarp();

#pragma unroll
    for (int nn = 0; nn < 8; nn++) {
        float acc0 = 0.f, acc1 = 0.f;
#pragma unroll
        for (int mm = 0; mm < 8; mm++) {
            float av = s[nn * 8 + mm];
            acc0 = fmaf(av, v[mm * 64 + lane], acc0);
            acc1 = fmaf(av, v[mm * 64 + 32 + lane], acc1);
        }
        g_o[base + nn * 768 + w * 64 + lane] =
            __uint_as_float(tf32r(acc0));
        g_o[base + nn * 768 + w * 64 + 32 + lane] =
            __uint_as_float(tf32r(acc1));
    }
    __syncthreads();

    if (tid < 64) {
        float sum = 0.f;
#pragma unroll
        for (int h = 0; h < 12; h++) sum += ss[h * 64 + tid];
        out[4194304 + (size_t)t * 64 + tid] = sum * (1.0f / 12.0f);
    }
}

// ============================================================
// launch
// ============================================================
#define SMEM_QKV (3 * (128 * AS_STRIDE + 32 * (256 + 8)) * 4)  // 156672
#define SMEM_FIN (3 * (64  * AS_STRIDE + 32 * (128 + 8)) * 4)  // 79872

extern "C" void kernel_launch(void* const* d_in, const int* in_sizes, int n_in,
                              void* d_out, int out_size) {
    const float* x  = (const float*)d_in[0];
    const float* wc = (const float*)d_in[1];
    const float* wq = (const float*)d_in[2];
    const float* wk = (const float*)d_in[3];
    const float* wv = (const float*)d_in[4];
    const float* wf = (const float*)d_in[5];
    float* out = (float*)d_out;

    float *gq, *gk, *gv, *go, *gc, *gxr, *gwq, *gwk, *gwv, *gwf;
    cudaGetSymbolAddress((void**)&gq, g_q);
    cudaGetSymbolAddress((void**)&gk, g_k);
    cudaGetSymbolAddress((void**)&gv, g_v);
    cudaGetSymbolAddress((void**)&go, g_o);
    cudaGetSymbolAddress((void**)&gc, g_comp);
    cudaGetSymbolAddress((void**)&gxr, g_xr);
    cudaGetSymbolAddress((void**)&gwq, g_wqr);
    cudaGetSymbolAddress((void**)&gwk, g_wkr);
    cudaGetSymbolAddress((void**)&gwv, g_wvr);
    cudaGetSymbolAddress((void**)&gwf, g_wfr);

    cudaFuncSetAttribute(attn_kernel,
                         cudaFuncAttributeMaxDynamicSharedMemorySize, SMEM_ATTN);
    cudaFuncSetAttribute(gemm_mma<128, 256, 512>,
                         cudaFuncAttributeMaxDynamicSharedMemorySize, SMEM_QKV);
    cudaFuncSetAttribute(gemm_mma<64, 128, 256>,
                         cudaFuncAttributeMaxDynamicSharedMemorySize, SMEM_FIN);

    // one merged tf32 pre-round pass (x + 4 weights)
    round_all<<<(TOT4 + 255) / 256, 256>>>(x, wq, wk, wv, wf,
                                           gxr, gwq, gwk, gwv, gwf);

    // A: gating (full-precision x)
    comp_kernel<<<512, 256>>>(x, wc);

    // B: fused QKV tf32 GEMMs. 9 = 3 matrices x 3 col-tiles of 256. KC=4.
    dim3 gB(32, 9, 8);
    gemm_mma<128, 256, 512><<<gB, 512, SMEM_QKV>>>(
        gxr, 1024, 128,
        gwq, gwk, gwv, 768, 98304, 3,
        gq, gk, gv, 6144, 768,
        4, gc);

    // C: attention over the block axis + score_mean
    attn_kernel<<<TOK, 384, SMEM_ATTN>>>(out);

    // D: final tf32 GEMM. K=768 -> KC=24, m-tile 64.
    dim3 gD(64, 1, 8);
    gemm_mma<64, 128, 256><<<gD, 256, SMEM_FIN>>>(
        go, 6144, 768,
        gwf, gwf, gwf, 128, 98304, 1,
        out, out, out, 1024, 128,
        24, nullptr);
}

// round 7
// speedup vs baseline: 1.0112x; 1.0112x over previous
#include <cuda_runtime.h>
#include <cuda_fp16.h>
#include <cstdint>

#define TOK 4096
#define QKV_ELEMS ((size_t)TOK * 6144)

// ---- scratch ----
__device__ float  g_comp[TOK * 8];
__device__ __half g_q[QKV_ELEMS];
__device__ __half g_k[QKV_ELEMS];
__device__ __half g_v[QKV_ELEMS];
__device__ float  g_o[QKV_ELEMS];
// tf32-pre-rounded operands
__device__ float g_xr[4194304];
__device__ float g_wqr[786432];
__device__ float g_wkr[786432];
__device__ float g_wvr[786432];
__device__ float g_wfr[786432];

// ============================================================
// helpers
// ============================================================
__device__ __forceinline__ uint32_t smem_u32(const void* p) {
    uint32_t a;
    asm("{ .reg .u64 t; cvta.to.shared.u64 t, %1; cvt.u32.u64 %0, t; }"
        : "=r"(a) : "l"(p));
    return a;
}
__device__ __forceinline__ uint32_t tf32r(float x) {
    uint32_t u;
    asm("cvt.rna.tf32.f32 %0, %1;" : "=r"(u) : "f"(x));
    return u;
}
__device__ __forceinline__ void cp16(uint32_t dst, const void* src) {
    asm volatile("cp.async.ca.shared.global [%0], [%1], 16;"
                 :: "r"(dst), "l"(src));
}
#define CP_COMMIT() asm volatile("cp.async.commit_group;" ::: "memory")
#define CP_WAIT(n)  asm volatile("cp.async.wait_group %0;" :: "n"(n) : "memory")

__device__ __forceinline__ void mma_tf32(float* c, const uint32_t* a,
                                         const uint32_t* b) {
    asm volatile(
        "mma.sync.aligned.m16n8k8.row.col.f32.tf32.tf32.f32 "
        "{%0,%1,%2,%3}, {%4,%5,%6,%7}, {%8,%9}, {%0,%1,%2,%3};"
        : "+f"(c[0]), "+f"(c[1]), "+f"(c[2]), "+f"(c[3])
        : "r"(a[0]), "r"(a[1]), "r"(a[2]), "r"(a[3]), "r"(b[0]), "r"(b[1]));
}

// ============================================================
// merged tf32 pre-round pass: x + 4 weight tensors, one launch
// ============================================================
#define X4   1048576
#define W4   196608
#define TOT4 (X4 + 4 * W4)

__global__ void round_all(const float* __restrict__ x,
                          const float* __restrict__ wq,
                          const float* __restrict__ wk,
                          const float* __restrict__ wv,
                          const float* __restrict__ wf,
                          float* __restrict__ xo, float* __restrict__ qo,
                          float* __restrict__ ko, float* __restrict__ vo,
                          float* __restrict__ fo) {
    int i = blockIdx.x * blockDim.x + threadIdx.x;
    if (i >= TOT4) return;
    const float4* src;
    float4* dst;
    int j = i;
    if (j < X4)                { src = (const float4*)x;  dst = (float4*)xo; }
    else if ((j -= X4) < W4)   { src = (const float4*)wq; dst = (float4*)qo; }
    else if ((j -= W4) < W4)   { src = (const float4*)wk; dst = (float4*)ko; }
    else if ((j -= W4) < W4)   { src = (const float4*)wv; dst = (float4*)vo; }
    else { j -= W4;              src = (const float4*)wf; dst = (float4*)fo; }
    float4 v = src[j];
    v.x = __uint_as_float(tf32r(v.x));
    v.y = __uint_as_float(tf32r(v.y));
    v.z = __uint_as_float(tf32r(v.z));
    v.w = __uint_as_float(tf32r(v.w));
    dst[j] = v;
}

// ============================================================
// Kernel A: competition gating
// ============================================================
__global__ void comp_kernel(const float* __restrict__ x,
                            const float* __restrict__ wc) {
    int gtid = blockIdx.x * blockDim.x + threadIdx.x;
    int t    = gtid >> 5;
    int lane = gtid & 31;
    if (t >= TOK) return;
    const float* xr = x + (size_t)t * 1024;

    float logit[8];
#pragma unroll
    for (int n = 0; n < 8; n++) {
        const float* xb = xr + n * 128;
        const float* wb = wc + n * 128;
        float p = xb[lane]      * wb[lane]
                + xb[lane + 32] * wb[lane + 32]
                + xb[lane + 64] * wb[lane + 64]
                + xb[lane + 96] * wb[lane + 96];
#pragma unroll
        for (int o = 16; o > 0; o >>= 1) p += __shfl_xor_sync(0xffffffffu, p, o);
        logit[n] = p;
    }
    float mx = logit[0];
#pragma unroll
    for (int n = 1; n < 8; n++) mx = fmaxf(mx, logit[n]);
    float s = 0.f, ev = 0.f;
#pragma unroll
    for (int n = 0; n < 8; n++) {
        float e = __expf(logit[n] - mx);
        s += e;
        if (lane == n) ev = e;
    }
    if (lane < 8) g_comp[t * 8 + lane] = ev / s;
}

// ============================================================
// tf32 mma.sync block-GEMM, templated tile + output type.
//   MT x NT CTA tile, NTHR threads, 3-stage cp.async, k-chunk 32.
// ============================================================
#define AS_STRIDE 36

template<int MT, int NT, int NTHR, typename OT>
__global__ __launch_bounds__(NTHR, 2)
void gemm_mma(const float* __restrict__ Abase, int lda, int a_blk,
              const float* __restrict__ W0, const float* __restrict__ W1,
              const float* __restrict__ W2, int ldb, int w_blk, int TPM,
              OT* __restrict__ C0, OT* __restrict__ C1,
              OT* __restrict__ C2, int ldc, int c_blk,
              int KC, const float* __restrict__ comp) {
    constexpr int BSS   = NT + 8;
    constexpr int A_BUF = MT * AS_STRIDE;
    constexpr int B_BUF = 32 * BSS;
    constexpr int STG   = A_BUF + B_BUF;
    constexpr int NWM   = MT / 32;
    constexpr int NWN   = (NTHR / 32) / NWM;
    constexpr int WNW   = NT / NWN;
    constexpr int JN    = WNW / 8;

    extern __shared__ __align__(16) float sm[];
    const uint32_t sbase = smem_u32(sm);

    const int tid  = threadIdx.x;
    const int wid  = tid >> 5;
    const int lane = tid & 31;
    const int wm   = wid % NWM;
    const int wn   = wid / NWM;
    const int g    = lane >> 2;
    const int t    = lane & 3;

    const int mt   = blockIdx.x;
    const int yy   = blockIdx.y;
    const int zb   = blockIdx.z;
    const int mat  = yy / TPM;
    const int col0 = (yy % TPM) * NT;

    const float* W = (mat == 0 ? W0 : (mat == 1 ? W1 : W2)) +
                     (size_t)zb * w_blk + col0;
    OT* C = (mat == 0 ? C0 : (mat == 1 ? C1 : C2)) +
            (size_t)zb * c_blk + col0;
    const float* A = Abase + (size_t)mt * MT * lda + (size_t)zb * a_blk;

    const int a_m  = tid >> 3;
    const int a_k4 = tid & 7;

    float acc[2][JN][4];
#pragma unroll
    for (int i = 0; i < 2; i++)
#pragma unroll
        for (int j = 0; j < JN; j++)
#pragma unroll
            for (int c = 0; c < 4; c++) acc[i][j][c] = 0.f;

    auto issue_chunk = [&](int kc) {
        const int st = kc % 3;
        const uint32_t ad = sbase + (uint32_t)(st * STG) * 4;
        const uint32_t bd = ad + (uint32_t)A_BUF * 4;
        const int k0 = kc * 32;
#pragma unroll
        for (int p = 0; p < MT * 8 / NTHR; p++) {
            int m = a_m + p * (NTHR / 8);
            cp16(ad + (uint32_t)(m * AS_STRIDE + a_k4 * 4) * 4,
                 A + (size_t)m * lda + k0 + a_k4 * 4);
        }
#pragma unroll
        for (int p = 0; p < 32 * (NT / 4) / NTHR; p++) {
            int idx = p * NTHR + tid;
            int k   = idx / (NT / 4);
            int e4  = idx % (NT / 4);
            cp16(bd + (uint32_t)(k * BSS + e4 * 4) * 4,
                 W + (size_t)(k0 + k) * ldb + e4 * 4);
        }
    };

    issue_chunk(0);
    CP_COMMIT();
    if (KC > 1) { issue_chunk(1); CP_COMMIT(); }

    for (int kc = 0; kc < KC; kc++) {
        if (kc + 1 < KC) { CP_WAIT(1); } else { CP_WAIT(0); }
        __syncthreads();
        if (kc + 2 < KC) { issue_chunk(kc + 2); CP_COMMIT(); }

        const float* as = sm + (kc % 3) * STG;
        const float* bs = as + A_BUF;
#pragma unroll
        for (int ks = 0; ks < 4; ks++) {
            const int kk = ks * 8;
            uint32_t af[2][4];
#pragma unroll
            for (int i = 0; i < 2; i++) {
                const int r0 = wm * 32 + i * 16;
                af[i][0] = __float_as_uint(as[(r0 + g)     * AS_STRIDE + kk + t]);
                af[i][1] = __float_as_uint(as[(r0 + g + 8) * AS_STRIDE + kk + t]);
                af[i][2] = __float_as_uint(as[(r0 + g)     * AS_STRIDE + kk + t + 4]);
                af[i][3] = __float_as_uint(as[(r0 + g + 8) * AS_STRIDE + kk + t + 4]);
            }
            uint32_t bf[JN][2];
#pragma unroll
            for (int j = 0; j < JN; j++) {
                const int c = wn * WNW + j * 8 + g;
                bf[j][0] = __float_as_uint(bs[(kk + t)     * BSS + c]);
                bf[j][1] = __float_as_uint(bs[(kk + t + 4) * BSS + c]);
            }
#pragma unroll
            for (int i = 0; i < 2; i++)
#pragma unroll
                for (int j = 0; j < JN; j++)
                    mma_tf32(acc[i][j], af[i], bf[j]);
        }
    }

    // ---- epilogue ----
#pragma unroll
    for (int i = 0; i < 2; i++) {
        const int r0 = mt * MT + wm * 32 + i * 16 + g;
        const int r1 = r0 + 8;
        float sc0 = 1.f, sc1 = 1.f;
        if (comp) { sc0 = comp[r0 * 8 + zb]; sc1 = comp[r1 * 8 + zb]; }
        OT* Cr0 = C + (size_t)r0 * ldc;
        OT* Cr1 = C + (size_t)r1 * ldc;
#pragma unroll
        for (int j = 0; j < JN; j++) {
            const int c = wn * WNW + j * 8 + 2 * t;
            if constexpr (sizeof(OT) == 2) {
                *(__half2*)((__half*)Cr0 + c) =
                    __floats2half2_rn(acc[i][j][0] * sc0, acc[i][j][1] * sc0);
                *(__half2*)((__half*)Cr1 + c) =
                    __floats2half2_rn(acc[i][j][2] * sc1, acc[i][j][3] * sc1);
            } else {
                *(float2*)((float*)Cr0 + c) =
                    make_float2(acc[i][j][0] * sc0, acc[i][j][1] * sc0);
                *(float2*)((float*)Cr1 + c) =
                    make_float2(acc[i][j][2] * sc1, acc[i][j][3] * sc1);
            }
        }
    }
}

// ============================================================
// Kernel C: block-attention per token. q/k/v read as fp16,
// staged fp32 in smem; o written fp32 (tf32-rounded).
// ============================================================
#define SMEM_ATTN ((12*8*65 + 12*8*65 + 12*8*64 + 12*64) * 4)

__global__ void attn_kernel(float* __restrict__ out) {
    extern __shared__ float smf[];
    float* sq = smf;
    float* sk = sq + 6240;
    float* sv = sk + 6240;
    float* ss = sv + 6144;

    const int t   = blockIdx.x;
    const int tid = threadIdx.x;
    const size_t base = (size_t)t * 6144;

    const __half* hq = g_q + base;
    const __half* hk = g_k + base;
    const __half* hv = g_v + base;

#pragma unroll
    for (int it = 0; it < 2; it++) {
        int idx8 = (it * 384 + tid) * 8;
        int nn  = idx8 / 768;
        int r   = idx8 - nn * 768;
        int h   = r >> 6;
        int j   = r & 63;
        float* dq = sq + h * 520 + nn * 65 + j;
        float* dk = sk + h * 520 + nn * 65 + j;
        float* dv = sv + h * 512 + nn * 64 + j;

        int4 vq = *(const int4*)(hq + idx8);
        int4 vk = *(const int4*)(hk + idx8);
        int4 vv = *(const int4*)(hv + idx8);
        const __half2* pq = (const __half2*)&vq;
        const __half2* pk = (const __half2*)&vk;
        const __half2* pv = (const __half2*)&vv;
#pragma unroll
        for (int p = 0; p < 4; p++) {
            float2 fq = __half22float2(pq[p]);
            float2 fk = __half22float2(pk[p]);
            float2 fv = __half22float2(pv[p]);
            dq[2 * p]     = fq.x * 0.125f;
            dq[2 * p + 1] = fq.y * 0.125f;
            dk[2 * p]     = fk.x;
            dk[2 * p + 1] = fk.y;
            dv[2 * p]     = fv.x;
            dv[2 * p + 1] = fv.y;
        }
    }
    __syncthreads();

    const int w    = tid >> 5;
    const int lane = tid & 31;
    float* q = sq + w * 520;
    float* k = sk + w * 520;
    float* v = sv + w * 512;
    float* s = ss + w * 64;

    const int nr = lane >> 3;
    const int mc = lane & 7;

    float s0 = 0.f, s1 = 0.f;
#pragma unroll
    for (int j = 0; j < 64; j++) {
        float kv = k[mc * 65 + j];
        s0 = fmaf(q[nr * 65 + j], kv, s0);
        s1 = fmaf(q[(nr + 4) * 65 + j], kv, s1);
    }
    float m0 = s0, m1 = s1;
#pragma unroll
    for (int o = 1; o < 8; o <<= 1) {
        m0 = fmaxf(m0, __shfl_xor_sync(0xffffffffu, m0, o));
        m1 = fmaxf(m1, __shfl_xor_sync(0xffffffffu, m1, o));
    }
    float e0 = __expf(s0 - m0), e1 = __expf(s1 - m1);
    float d0 = e0, d1 = e1;
#pragma unroll
    for (int o = 1; o < 8; o <<= 1) {
        d0 += __shfl_xor_sync(0xffffffffu, d0, o);
        d1 += __shfl_xor_sync(0xffffffffu, d1, o);
    }
    float a0 = e0 / d0, a1 = e1 / d1;
    s[nr * 8 + mc]       = a0;
    s[(nr + 4) * 8 + mc] = a1;
    __syncwarp();

#pragma unroll
    for (int nn = 0; nn < 8; nn++) {
        float acc0 = 0.f, acc1 = 0.f;
#pragma unroll
        for (int mm = 0; mm < 8; mm++) {
            float av = s[nn * 8 + mm];
            acc0 = fmaf(av, v[mm * 64 + lane], acc0);
            acc1 = fmaf(av, v[mm * 64 + 32 + lane], acc1);
        }
        g_o[base + nn * 768 + w * 64 + lane] =
            __uint_as_float(tf32r(acc0));
        g_o[base + nn * 768 + w * 64 + 32 + lane] =
            __uint_as_float(tf32r(acc1));
    }
    __syncthreads();

    if (tid < 64) {
        float sum = 0.f;
#pragma unroll
        for (int h = 0; h < 12; h++) sum += ss[h * 64 + tid];
        out[4194304 + (size_t)t * 64 + tid] = sum * (1.0f / 12.0f);
    }
}

// ============================================================
// launch
// ============================================================
#define SMEM_QKV (3 * (128 * AS_STRIDE + 32 * (128 + 8)) * 4)  // 107520
#define SMEM_FIN (3 * (64  * AS_STRIDE + 32 * (128 + 8)) * 4)  // 79872

extern "C" void kernel_launch(void* const* d_in, const int* in_sizes, int n_in,
                              void* d_out, int out_size) {
    const float* x  = (const float*)d_in[0];
    const float* wc = (const float*)d_in[1];
    const float* wq = (const float*)d_in[2];
    const float* wk = (const float*)d_in[3];
    const float* wv = (const float*)d_in[4];
    const float* wf = (const float*)d_in[5];
    float* out = (float*)d_out;

    __half *gq, *gk, *gv;
    float *go, *gc, *gxr, *gwq, *gwk, *gwv, *gwf;
    cudaGetSymbolAddress((void**)&gq, g_q);
    cudaGetSymbolAddress((void**)&gk, g_k);
    cudaGetSymbolAddress((void**)&gv, g_v);
    cudaGetSymbolAddress((void**)&go, g_o);
    cudaGetSymbolAddress((void**)&gc, g_comp);
    cudaGetSymbolAddress((void**)&gxr, g_xr);
    cudaGetSymbolAddress((void**)&gwq, g_wqr);
    cudaGetSymbolAddress((void**)&gwk, g_wkr);
    cudaGetSymbolAddress((void**)&gwv, g_wvr);
    cudaGetSymbolAddress((void**)&gwf, g_wfr);

    cudaFuncSetAttribute(attn_kernel,
                         cudaFuncAttributeMaxDynamicSharedMemorySize, SMEM_ATTN);
    cudaFuncSetAttribute(gemm_mma<128, 128, 256, __half>,
                         cudaFuncAttributeMaxDynamicSharedMemorySize, SMEM_QKV);
    cudaFuncSetAttribute(gemm_mma<64, 128, 256, float>,
                         cudaFuncAttributeMaxDynamicSharedMemorySize, SMEM_FIN);

    // one merged tf32 pre-round pass (x + 4 weights)
    round_all<<<(TOT4 + 255) / 256, 256>>>(x, wq, wk, wv, wf,
                                           gxr, gwq, gwk, gwv, gwf);

    // A: gating (full-precision x)
    comp_kernel<<<512, 256>>>(x, wc);

    // B: fused QKV tf32 GEMMs (fp16 outputs). 18 = 3 mats x 6 col-tiles. KC=4.
    dim3 gB(32, 18, 8);
    gemm_mma<128, 128, 256, __half><<<gB, 256, SMEM_QKV>>>(
        gxr, 1024, 128,
        gwq, gwk, gwv, 768, 98304, 6,
        gq, gk, gv, 6144, 768,
        4, gc);

    // C: attention over the block axis + score_mean
    attn_kernel<<<TOK, 384, SMEM_ATTN>>>(out);

    // D: final tf32 GEMM (fp32 output). K=768 -> KC=24, m-tile 64.
    dim3 gD(64, 1, 8);
    gemm_mma<64, 128, 256, float><<<gD, 256, SMEM_FIN>>>(
        go, 6144, 768,
        gwf, gwf, gwf, 128, 98304, 1,
        out, out, out, 1024, 128,
        24, nullptr);
}

// round 8
// speedup vs baseline: 1.1418x; 1.1292x over previous
#include <cuda_runtime.h>
#include <cuda_fp16.h>
#include <cstdint>

#define TOK 4096
#define QKV_ELEMS ((size_t)TOK * 6144)

// ---- scratch ----
__device__ float  g_comp[TOK * 8];
__device__ __half g_q[QKV_ELEMS];
__device__ __half g_k[QKV_ELEMS];
__device__ __half g_v[QKV_ELEMS];
__device__ float  g_o[QKV_ELEMS];
// tf32-pre-rounded operands
__device__ float g_xr[4194304];
__device__ float g_wqr[786432];
__device__ float g_wkr[786432];
__device__ float g_wvr[786432];
__device__ float g_wfr[786432];

// ============================================================
// helpers
// ============================================================
__device__ __forceinline__ uint32_t smem_u32(const void* p) {
    uint32_t a;
    asm("{ .reg .u64 t; cvta.to.shared.u64 t, %1; cvt.u32.u64 %0, t; }"
        : "=r"(a) : "l"(p));
    return a;
}
__device__ __forceinline__ uint32_t tf32r(float x) {
    uint32_t u;
    asm("cvt.rna.tf32.f32 %0, %1;" : "=r"(u) : "f"(x));
    return u;
}
__device__ __forceinline__ void cp16(uint32_t dst, const void* src) {
    asm volatile("cp.async.ca.shared.global [%0], [%1], 16;"
                 :: "r"(dst), "l"(src));
}
#define CP_COMMIT() asm volatile("cp.async.commit_group;" ::: "memory")
#define CP_WAIT(n)  asm volatile("cp.async.wait_group %0;" :: "n"(n) : "memory")

__device__ __forceinline__ void mma_tf32(float* c, const uint32_t* a,
                                         const uint32_t* b) {
    asm volatile(
        "mma.sync.aligned.m16n8k8.row.col.f32.tf32.tf32.f32 "
        "{%0,%1,%2,%3}, {%4,%5,%6,%7}, {%8,%9}, {%0,%1,%2,%3};"
        : "+f"(c[0]), "+f"(c[1]), "+f"(c[2]), "+f"(c[3])
        : "r"(a[0]), "r"(a[1]), "r"(a[2]), "r"(a[3]), "r"(b[0]), "r"(b[1]));
}

// ============================================================
// merged tf32 pre-round pass
// ============================================================
#define X4   1048576
#define W4   196608
#define TOT4 (X4 + 4 * W4)

__global__ void round_all(const float* __restrict__ x,
                          const float* __restrict__ wq,
                          const float* __restrict__ wk,
                          const float* __restrict__ wv,
                          const float* __restrict__ wf,
                          float* __restrict__ xo, float* __restrict__ qo,
                          float* __restrict__ ko, float* __restrict__ vo,
                          float* __restrict__ fo) {
    int i = blockIdx.x * blockDim.x + threadIdx.x;
    if (i >= TOT4) return;
    const float4* src;
    float4* dst;
    int j = i;
    if (j < X4)                { src = (const float4*)x;  dst = (float4*)xo; }
    else if ((j -= X4) < W4)   { src = (const float4*)wq; dst = (float4*)qo; }
    else if ((j -= W4) < W4)   { src = (const float4*)wk; dst = (float4*)ko; }
    else if ((j -= W4) < W4)   { src = (const float4*)wv; dst = (float4*)vo; }
    else { j -= W4;              src = (const float4*)wf; dst = (float4*)fo; }
    float4 v = src[j];
    v.x = __uint_as_float(tf32r(v.x));
    v.y = __uint_as_float(tf32r(v.y));
    v.z = __uint_as_float(tf32r(v.z));
    v.w = __uint_as_float(tf32r(v.w));
    dst[j] = v;
}

// ============================================================
// Kernel A: competition gating
// ============================================================
__global__ void comp_kernel(const float* __restrict__ x,
                            const float* __restrict__ wc) {
    int gtid = blockIdx.x * blockDim.x + threadIdx.x;
    int t    = gtid >> 5;
    int lane = gtid & 31;
    if (t >= TOK) return;
    const float* xr = x + (size_t)t * 1024;

    float logit[8];
#pragma unroll
    for (int n = 0; n < 8; n++) {
        const float* xb = xr + n * 128;
        const float* wb = wc + n * 128;
        float p = xb[lane]      * wb[lane]
                + xb[lane + 32] * wb[lane + 32]
                + xb[lane + 64] * wb[lane + 64]
                + xb[lane + 96] * wb[lane + 96];
#pragma unroll
        for (int o = 16; o > 0; o >>= 1) p += __shfl_xor_sync(0xffffffffu, p, o);
        logit[n] = p;
    }
    float mx = logit[0];
#pragma unroll
    for (int n = 1; n < 8; n++) mx = fmaxf(mx, logit[n]);
    float s = 0.f, ev = 0.f;
#pragma unroll
    for (int n = 0; n < 8; n++) {
        float e = __expf(logit[n] - mx);
        s += e;
        if (lane == n) ev = e;
    }
    if (lane < 8) g_comp[t * 8 + lane] = ev / s;
}

// ============================================================
// tf32 mma.sync block-GEMM (unchanged from R7)
// ============================================================
#define AS_STRIDE 36

template<int MT, int NT, int NTHR, typename OT>
__global__ __launch_bounds__(NTHR, 2)
void gemm_mma(const float* __restrict__ Abase, int lda, int a_blk,
              const float* __restrict__ W0, const float* __restrict__ W1,
              const float* __restrict__ W2, int ldb, int w_blk, int TPM,
              OT* __restrict__ C0, OT* __restrict__ C1,
              OT* __restrict__ C2, int ldc, int c_blk,
              int KC, const float* __restrict__ comp) {
    constexpr int BSS   = NT + 8;
    constexpr int A_BUF = MT * AS_STRIDE;
    constexpr int B_BUF = 32 * BSS;
    constexpr int STG   = A_BUF + B_BUF;
    constexpr int NWM   = MT / 32;
    constexpr int NWN   = (NTHR / 32) / NWM;
    constexpr int WNW   = NT / NWN;
    constexpr int JN    = WNW / 8;

    extern __shared__ __align__(16) float sm[];
    const uint32_t sbase = smem_u32(sm);

    const int tid  = threadIdx.x;
    const int wid  = tid >> 5;
    const int lane = tid & 31;
    const int wm   = wid % NWM;
    const int wn   = wid / NWM;
    const int g    = lane >> 2;
    const int t    = lane & 3;

    const int mt   = blockIdx.x;
    const int yy   = blockIdx.y;
    const int zb   = blockIdx.z;
    const int mat  = yy / TPM;
    const int col0 = (yy % TPM) * NT;

    const float* W = (mat == 0 ? W0 : (mat == 1 ? W1 : W2)) +
                     (size_t)zb * w_blk + col0;
    OT* C = (mat == 0 ? C0 : (mat == 1 ? C1 : C2)) +
            (size_t)zb * c_blk + col0;
    const float* A = Abase + (size_t)mt * MT * lda + (size_t)zb * a_blk;

    const int a_m  = tid >> 3;
    const int a_k4 = tid & 7;

    float acc[2][JN][4];
#pragma unroll
    for (int i = 0; i < 2; i++)
#pragma unroll
        for (int j = 0; j < JN; j++)
#pragma unroll
            for (int c = 0; c < 4; c++) acc[i][j][c] = 0.f;

    auto issue_chunk = [&](int kc) {
        const int st = kc % 3;
        const uint32_t ad = sbase + (uint32_t)(st * STG) * 4;
        const uint32_t bd = ad + (uint32_t)A_BUF * 4;
        const int k0 = kc * 32;
#pragma unroll
        for (int p = 0; p < MT * 8 / NTHR; p++) {
            int m = a_m + p * (NTHR / 8);
            cp16(ad + (uint32_t)(m * AS_STRIDE + a_k4 * 4) * 4,
                 A + (size_t)m * lda + k0 + a_k4 * 4);
        }
#pragma unroll
        for (int p = 0; p < 32 * (NT / 4) / NTHR; p++) {
            int idx = p * NTHR + tid;
            int k   = idx / (NT / 4);
            int e4  = idx % (NT / 4);
            cp16(bd + (uint32_t)(k * BSS + e4 * 4) * 4,
                 W + (size_t)(k0 + k) * ldb + e4 * 4);
        }
    };

    issue_chunk(0);
    CP_COMMIT();
    if (KC > 1) { issue_chunk(1); CP_COMMIT(); }

    for (int kc = 0; kc < KC; kc++) {
        if (kc + 1 < KC) { CP_WAIT(1); } else { CP_WAIT(0); }
        __syncthreads();
        if (kc + 2 < KC) { issue_chunk(kc + 2); CP_COMMIT(); }

        const float* as = sm + (kc % 3) * STG;
        const float* bs = as + A_BUF;
#pragma unroll
        for (int ks = 0; ks < 4; ks++) {
            const int kk = ks * 8;
            uint32_t af[2][4];
#pragma unroll
            for (int i = 0; i < 2; i++) {
                const int r0 = wm * 32 + i * 16;
                af[i][0] = __float_as_uint(as[(r0 + g)     * AS_STRIDE + kk + t]);
                af[i][1] = __float_as_uint(as[(r0 + g + 8) * AS_STRIDE + kk + t]);
                af[i][2] = __float_as_uint(as[(r0 + g)     * AS_STRIDE + kk + t + 4]);
                af[i][3] = __float_as_uint(as[(r0 + g + 8) * AS_STRIDE + kk + t + 4]);
            }
            uint32_t bf[JN][2];
#pragma unroll
            for (int j = 0; j < JN; j++) {
                const int c = wn * WNW + j * 8 + g;
                bf[j][0] = __float_as_uint(bs[(kk + t)     * BSS + c]);
                bf[j][1] = __float_as_uint(bs[(kk + t + 4) * BSS + c]);
            }
#pragma unroll
            for (int i = 0; i < 2; i++)
#pragma unroll
                for (int j = 0; j < JN; j++)
                    mma_tf32(acc[i][j], af[i], bf[j]);
        }
    }

    // ---- epilogue ----
#pragma unroll
    for (int i = 0; i < 2; i++) {
        const int r0 = mt * MT + wm * 32 + i * 16 + g;
        const int r1 = r0 + 8;
        float sc0 = 1.f, sc1 = 1.f;
        if (comp) { sc0 = comp[r0 * 8 + zb]; sc1 = comp[r1 * 8 + zb]; }
        OT* Cr0 = C + (size_t)r0 * ldc;
        OT* Cr1 = C + (size_t)r1 * ldc;
#pragma unroll
        for (int j = 0; j < JN; j++) {
            const int c = wn * WNW + j * 8 + 2 * t;
            if constexpr (sizeof(OT) == 2) {
                *(__half2*)((__half*)Cr0 + c) =
                    __floats2half2_rn(acc[i][j][0] * sc0, acc[i][j][1] * sc0);
                *(__half2*)((__half*)Cr1 + c) =
                    __floats2half2_rn(acc[i][j][2] * sc1, acc[i][j][3] * sc1);
            } else {
                *(float2*)((float*)Cr0 + c) =
                    make_float2(acc[i][j][0] * sc0, acc[i][j][1] * sc0);
                *(float2*)((float*)Cr1 + c) =
                    make_float2(acc[i][j][2] * sc1, acc[i][j][3] * sc1);
            }
        }
    }
}

// ============================================================
// Kernel C: register/shuffle block-attention.
// CTA = token (384 thr), warp = head. Lane (n = l>>2, p = l&3)
// owns j-slice [p*16, p*16+16) of q/k/v row n, in registers.
// ============================================================
__global__ __launch_bounds__(384, 2)
void attn_kernel(float* __restrict__ out) {
    __shared__ float ss[12 * 64];

    const int t    = blockIdx.x;
    const int tid  = threadIdx.x;
    const int w    = tid >> 5;      // head
    const int lane = tid & 31;
    const int n    = lane >> 2;
    const int p    = lane & 3;

    const size_t base = (size_t)t * 6144 + (size_t)n * 768 + w * 64 + p * 16;

    // ---- load q/k/v slices (fp16, 2x int4 each) ----
    uint4 qa = *(const uint4*)(g_q + base);
    uint4 qb = *(const uint4*)(g_q + base + 8);
    uint4 ka = *(const uint4*)(g_k + base);
    uint4 kb = *(const uint4*)(g_k + base + 8);
    uint4 va = *(const uint4*)(g_v + base);
    uint4 vb = *(const uint4*)(g_v + base + 8);

    uint32_t kh[8] = {ka.x, ka.y, ka.z, ka.w, kb.x, kb.y, kb.z, kb.w};
    uint32_t vh[8] = {va.x, va.y, va.z, va.w, vb.x, vb.y, vb.z, vb.w};

    float qf[16];
    {
        const uint32_t qh[8] = {qa.x, qa.y, qa.z, qa.w, qb.x, qb.y, qb.z, qb.w};
#pragma unroll
        for (int r = 0; r < 8; r++) {
            float2 f = __half22float2(*(const __half2*)&qh[r]);
            qf[2 * r]     = f.x * 0.125f;   // hd^-0.5
            qf[2 * r + 1] = f.y * 0.125f;
        }
    }

    // ---- scores: sc[m] = q[n] . k[m]  (partial over j-slice, then reduce p) ----
    float sc[8];
#pragma unroll
    for (int m = 0; m < 8; m++) {
        const int src = m * 4 + p;
        float a = 0.f;
#pragma unroll
        for (int r = 0; r < 8; r++) {
            uint32_t kk = __shfl_sync(0xffffffffu, kh[r], src);
            float2 f = __half22float2(*(const __half2*)&kk);
            a = fmaf(qf[2 * r], f.x, a);
            a = fmaf(qf[2 * r + 1], f.y, a);
        }
        sc[m] = a;
    }
#pragma unroll
    for (int o = 1; o <= 2; o <<= 1)
#pragma unroll
        for (int m = 0; m < 8; m++)
            sc[m] += __shfl_xor_sync(0xffffffffu, sc[m], o);

    // ---- softmax over m (in registers, all lanes of group n identical) ----
    float mx = sc[0];
#pragma unroll
    for (int m = 1; m < 8; m++) mx = fmaxf(mx, sc[m]);
    float den = 0.f;
#pragma unroll
    for (int m = 0; m < 8; m++) { sc[m] = __expf(sc[m] - mx); den += sc[m]; }
    const float inv = 1.0f / den;
#pragma unroll
    for (int m = 0; m < 8; m++) sc[m] *= inv;

    // score_mean contribution
    if (p == 0) {
#pragma unroll
        for (int m = 0; m < 8; m++) ss[w * 64 + n * 8 + m] = sc[m];
    }

    // ---- out[n][j-slice] = sum_m a[m] * v[m][j-slice] ----
    float of[16];
#pragma unroll
    for (int r = 0; r < 16; r++) of[r] = 0.f;
#pragma unroll
    for (int m = 0; m < 8; m++) {
        const int src = m * 4 + p;
        const float a = sc[m];
#pragma unroll
        for (int r = 0; r < 8; r++) {
            uint32_t vv = __shfl_sync(0xffffffffu, vh[r], src);
            float2 f = __half22float2(*(const __half2*)&vv);
            of[2 * r]     = fmaf(a, f.x, of[2 * r]);
            of[2 * r + 1] = fmaf(a, f.y, of[2 * r + 1]);
        }
    }
    // tf32-round and store 4x float4 (64B contiguous per lane)
    float* dst = g_o + base;
#pragma unroll
    for (int r = 0; r < 4; r++) {
        float4 o;
        o.x = __uint_as_float(tf32r(of[4 * r + 0]));
        o.y = __uint_as_float(tf32r(of[4 * r + 1]));
        o.z = __uint_as_float(tf32r(of[4 * r + 2]));
        o.w = __uint_as_float(tf32r(of[4 * r + 3]));
        *(float4*)(dst + 4 * r) = o;
    }

    __syncthreads();
    if (tid < 64) {
        float sum = 0.f;
#pragma unroll
        for (int h = 0; h < 12; h++) sum += ss[h * 64 + tid];
        out[4194304 + (size_t)t * 64 + tid] = sum * (1.0f / 12.0f);
    }
}

// ============================================================
// launch
// ============================================================
#define SMEM_QKV (3 * (128 * AS_STRIDE + 32 * (128 + 8)) * 4)  // 107520
#define SMEM_FIN (3 * (64  * AS_STRIDE + 32 * (128 + 8)) * 4)  // 79872

extern "C" void kernel_launch(void* const* d_in, const int* in_sizes, int n_in,
                              void* d_out, int out_size) {
    const float* x  = (const float*)d_in[0];
    const float* wc = (const float*)d_in[1];
    const float* wq = (const float*)d_in[2];
    const float* wk = (const float*)d_in[3];
    const float* wv = (const float*)d_in[4];
    const float* wf = (const float*)d_in[5];
    float* out = (float*)d_out;

    __half *gq, *gk, *gv;
    float *go, *gc, *gxr, *gwq, *gwk, *gwv, *gwf;
    cudaGetSymbolAddress((void**)&gq, g_q);
    cudaGetSymbolAddress((void**)&gk, g_k);
    cudaGetSymbolAddress((void**)&gv, g_v);
    cudaGetSymbolAddress((void**)&go, g_o);
    cudaGetSymbolAddress((void**)&gc, g_comp);
    cudaGetSymbolAddress((void**)&gxr, g_xr);
    cudaGetSymbolAddress((void**)&gwq, g_wqr);
    cudaGetSymbolAddress((void**)&gwk, g_wkr);
    cudaGetSymbolAddress((void**)&gwv, g_wvr);
    cudaGetSymbolAddress((void**)&gwf, g_wfr);

    cudaFuncSetAttribute(gemm_mma<128, 128, 256, __half>,
                         cudaFuncAttributeMaxDynamicSharedMemorySize, SMEM_QKV);
    cudaFuncSetAttribute(gemm_mma<64, 128, 256, float>,
                         cudaFuncAttributeMaxDynamicSharedMemorySize, SMEM_FIN);

    // one merged tf32 pre-round pass (x + 4 weights)
    round_all<<<(TOT4 + 255) / 256, 256>>>(x, wq, wk, wv, wf,
                                           gxr, gwq, gwk, gwv, gwf);

    // A: gating (full-precision x)
    comp_kernel<<<512, 256>>>(x, wc);

    // B: fused QKV tf32 GEMMs (fp16 outputs). 18 = 3 mats x 6 col-tiles. KC=4.
    dim3 gB(32, 18, 8);
    gemm_mma<128, 128, 256, __half><<<gB, 256, SMEM_QKV>>>(
        gxr, 1024, 128,
        gwq, gwk, gwv, 768, 98304, 6,
        gq, gk, gv, 6144, 768,
        4, gc);

    // C: register/shuffle attention + score_mean
    attn_kernel<<<TOK, 384>>>(out);

    // D: final tf32 GEMM (fp32 output). K=768 -> KC=24, m-tile 64.
    dim3 gD(64, 1, 8);
    gemm_mma<64, 128, 256, float><<<gD, 256, SMEM_FIN>>>(
        go, 6144, 768,
        gwf, gwf, gwf, 128, 98304, 1,
        out, out, out, 1024, 128,
        24, nullptr);
}

// round 9
// speedup vs baseline: 1.4015x; 1.2274x over previous
#include <cuda_runtime.h>
#include <cuda_fp16.h>
#include <cstdint>

#define TOK 4096
#define QKV_ELEMS ((size_t)TOK * 6144)

// ---- scratch ----
__device__ float  g_comp[TOK * 8];
__device__ __half g_q[QKV_ELEMS];
__device__ __half g_k[QKV_ELEMS];
__device__ __half g_v[QKV_ELEMS];
__device__ float  g_o[QKV_ELEMS];
__device__ __half g_xh[4194304];          // x as fp16 [4096][1024]
__device__ __half2 g_wqh[393216];         // packed [8][64 kp][768 e]
__device__ __half2 g_wkh[393216];
__device__ __half2 g_wvh[393216];
__device__ float  g_wfr[786432];          // wf tf32-rounded

// ============================================================
// helpers
// ============================================================
__device__ __forceinline__ uint32_t smem_u32(const void* p) {
    uint32_t a;
    asm("{ .reg .u64 t; cvta.to.shared.u64 t, %1; cvt.u32.u64 %0, t; }"
        : "=r"(a) : "l"(p));
    return a;
}
__device__ __forceinline__ uint32_t tf32r(float x) {
    uint32_t u;
    asm("cvt.rna.tf32.f32 %0, %1;" : "=r"(u) : "f"(x));
    return u;
}
__device__ __forceinline__ void cp16(uint32_t dst, const void* src) {
    asm volatile("cp.async.ca.shared.global [%0], [%1], 16;"
                 :: "r"(dst), "l"(src));
}
#define CP_COMMIT() asm volatile("cp.async.commit_group;" ::: "memory")
#define CP_WAIT(n)  asm volatile("cp.async.wait_group %0;" :: "n"(n) : "memory")

__device__ __forceinline__ void mma_tf32(float* c, const uint32_t* a,
                                         const uint32_t* b) {
    asm volatile(
        "mma.sync.aligned.m16n8k8.row.col.f32.tf32.tf32.f32 "
        "{%0,%1,%2,%3}, {%4,%5,%6,%7}, {%8,%9}, {%0,%1,%2,%3};"
        : "+f"(c[0]), "+f"(c[1]), "+f"(c[2]), "+f"(c[3])
        : "r"(a[0]), "r"(a[1]), "r"(a[2]), "r"(a[3]), "r"(b[0]), "r"(b[1]));
}
__device__ __forceinline__ void mma_f16(float* c, const uint32_t* a,
                                        const uint32_t* b) {
    asm volatile(
        "mma.sync.aligned.m16n8k16.row.col.f32.f16.f16.f32 "
        "{%0,%1,%2,%3}, {%4,%5,%6,%7}, {%8,%9}, {%0,%1,%2,%3};"
        : "+f"(c[0]), "+f"(c[1]), "+f"(c[2]), "+f"(c[3])
        : "r"(a[0]), "r"(a[1]), "r"(a[2]), "r"(a[3]), "r"(b[0]), "r"(b[1]));
}

// ============================================================
// prep: x->fp16 | wq/wk/wv fp16-pack (k-pairs) | wf tf32-round
// ============================================================
#define NX4 1048576      // x float4 units
#define NWP 98304        // pack units per weight: 8 nb x 64 kp x 192 e4
#define NF4 196608       // wf float4 units
#define NPREP (NX4 + 3 * NWP + NF4)   // 1540096

__global__ void prep_kernel(const float* __restrict__ x,
                            const float* __restrict__ wq,
                            const float* __restrict__ wk,
                            const float* __restrict__ wv,
                            const float* __restrict__ wf) {
    int u = blockIdx.x * blockDim.x + threadIdx.x;
    if (u >= NPREP) return;
    if (u < NX4) {
        float4 v = ((const float4*)x)[u];
        __half2 h0 = __floats2half2_rn(v.x, v.y);
        __half2 h1 = __floats2half2_rn(v.z, v.w);
        *(uint2*)&g_xh[(size_t)u * 4] =
            make_uint2(*(uint32_t*)&h0, *(uint32_t*)&h1);
        return;
    }
    u -= NX4;
    if (u < 3 * NWP) {
        const float* w; __half2* o;
        if (u < NWP)            { w = wq; o = g_wqh; }
        else if (u < 2 * NWP)   { w = wk; o = g_wkh; u -= NWP; }
        else                    { w = wv; o = g_wvh; u -= 2 * NWP; }
        int e4 = u % 192;
        int kp = (u / 192) % 64;
        int nb = u / (192 * 64);
        const float* lo = w + (size_t)nb * 98304 + (size_t)(2 * kp) * 768 + e4 * 4;
        float4 l = *(const float4*)lo;
        float4 h = *(const float4*)(lo + 768);
        __half2 p[4];
        p[0] = __halves2half2(__float2half_rn(l.x), __float2half_rn(h.x));
        p[1] = __halves2half2(__float2half_rn(l.y), __float2half_rn(h.y));
        p[2] = __halves2half2(__float2half_rn(l.z), __float2half_rn(h.z));
        p[3] = __halves2half2(__float2half_rn(l.w), __float2half_rn(h.w));
        *(uint4*)&o[(size_t)nb * 49152 + (size_t)kp * 768 + e4 * 4] =
            *(uint4*)p;
        return;
    }
    u -= 3 * NWP;
    float4 v = ((const float4*)wf)[u];
    v.x = __uint_as_float(tf32r(v.x));
    v.y = __uint_as_float(tf32r(v.y));
    v.z = __uint_as_float(tf32r(v.z));
    v.w = __uint_as_float(tf32r(v.w));
    ((float4*)g_wfr)[u] = v;
}

// ============================================================
// Kernel A: competition gating
// ============================================================
__global__ void comp_kernel(const float* __restrict__ x,
                            const float* __restrict__ wc) {
    int gtid = blockIdx.x * blockDim.x + threadIdx.x;
    int t    = gtid >> 5;
    int lane = gtid & 31;
    if (t >= TOK) return;
    const float* xr = x + (size_t)t * 1024;

    float logit[8];
#pragma unroll
    for (int n = 0; n < 8; n++) {
        const float* xb = xr + n * 128;
        const float* wb = wc + n * 128;
        float p = xb[lane]      * wb[lane]
                + xb[lane + 32] * wb[lane + 32]
                + xb[lane + 64] * wb[lane + 64]
                + xb[lane + 96] * wb[lane + 96];
#pragma unroll
        for (int o = 16; o > 0; o >>= 1) p += __shfl_xor_sync(0xffffffffu, p, o);
        logit[n] = p;
    }
    float mx = logit[0];
#pragma unroll
    for (int n = 1; n < 8; n++) mx = fmaxf(mx, logit[n]);
    float s = 0.f, ev = 0.f;
#pragma unroll
    for (int n = 0; n < 8; n++) {
        float e = __expf(logit[n] - mx);
        s += e;
        if (lane == n) ev = e;
    }
    if (lane < 8) g_comp[t * 8 + lane] = ev / s;
}

// ============================================================
// fp16 QKV GEMM: per (mt, yy, zb) C[128x128] = A[128x128] @ W[128x128]
//   A smem [m][k] fp16 stride 40 halves (20 w); B smem [kp][n] half2
//   stride 136 w. 3-stage cp.async, k-chunk 32, 8 warps 4x2.
// ============================================================
#define QA_W 2560            // A words per stage (128*20)
#define QB_W 2176            // B words per stage (16*136)
#define QSTG_W (QA_W + QB_W) // 4736
#define SMEM_Q16 (3 * QSTG_W * 4)  // 56832

__global__ __launch_bounds__(256, 2)
void qkv16_kernel(const __half* __restrict__ Xh,
                  const uint32_t* __restrict__ WQ,
                  const uint32_t* __restrict__ WK,
                  const uint32_t* __restrict__ WV,
                  __half* __restrict__ CQ, __half* __restrict__ CK,
                  __half* __restrict__ CV,
                  const float* __restrict__ comp) {
    extern __shared__ __align__(16) uint32_t smw[];
    const uint32_t sbase = smem_u32(smw);

    const int tid  = threadIdx.x;
    const int wid  = tid >> 5;
    const int lane = tid & 31;
    const int wm   = wid & 3;
    const int wn   = wid >> 2;
    const int g    = lane >> 2;
    const int t    = lane & 3;

    const int mt   = blockIdx.x;
    const int yy   = blockIdx.y;
    const int zb   = blockIdx.z;
    const int mat  = yy / 6;
    const int col0 = (yy % 6) * 128;

    const uint32_t* Wh = (mat == 0 ? WQ : (mat == 1 ? WK : WV)) +
                         (size_t)zb * 49152 + col0;
    __half* C = (mat == 0 ? CQ : (mat == 1 ? CK : CV)) +
                (size_t)zb * 768 + col0;
    const __half* Ah = Xh + (size_t)(mt * 128) * 1024 + zb * 128;

    float acc[2][8][4];
#pragma unroll
    for (int i = 0; i < 2; i++)
#pragma unroll
        for (int j = 0; j < 8; j++)
#pragma unroll
            for (int c = 0; c < 4; c++) acc[i][j][c] = 0.f;

    auto issue_chunk = [&](int kc) {
        const int st = kc % 3;
        const uint32_t ad = sbase + (uint32_t)(st * QSTG_W) * 4;
        const uint32_t bd = ad + QA_W * 4;
        const int k0h = kc * 32;
#pragma unroll
        for (int p = 0; p < 2; p++) {
            int idx = p * 256 + tid;
            int r = idx >> 2, c16 = idx & 3;
            cp16(ad + (uint32_t)(r * 20 + c16 * 4) * 4,
                 Ah + (size_t)r * 1024 + k0h + c16 * 8);
        }
#pragma unroll
        for (int p = 0; p < 2; p++) {
            int idx = p * 256 + tid;
            int kpl = idx >> 5, c = idx & 31;
            cp16(bd + (uint32_t)(kpl * 136 + c * 4) * 4,
                 Wh + (size_t)(kc * 16 + kpl) * 768 + c * 4);
        }
    };

    issue_chunk(0);
    CP_COMMIT();
    issue_chunk(1);
    CP_COMMIT();

    for (int kc = 0; kc < 4; kc++) {
        if (kc + 1 < 4) { CP_WAIT(1); } else { CP_WAIT(0); }
        __syncthreads();
        if (kc + 2 < 4) { issue_chunk(kc + 2); CP_COMMIT(); }

        const uint32_t* aw = smw + (kc % 3) * QSTG_W;
        const uint32_t* bw = aw + QA_W;
#pragma unroll
        for (int ks = 0; ks < 2; ks++) {
            uint32_t af[2][4];
#pragma unroll
            for (int i = 0; i < 2; i++) {
                const int r0 = wm * 32 + i * 16;
                af[i][0] = aw[(r0 + g)     * 20 + ks * 8 + t];
                af[i][1] = aw[(r0 + g + 8) * 20 + ks * 8 + t];
                af[i][2] = aw[(r0 + g)     * 20 + ks * 8 + t + 4];
                af[i][3] = aw[(r0 + g + 8) * 20 + ks * 8 + t + 4];
            }
            uint32_t bf[8][2];
#pragma unroll
            for (int j = 0; j < 8; j++) {
                const int c = wn * 64 + j * 8 + g;
                bf[j][0] = bw[(ks * 8 + t)     * 136 + c];
                bf[j][1] = bw[(ks * 8 + 4 + t) * 136 + c];
            }
#pragma unroll
            for (int i = 0; i < 2; i++)
#pragma unroll
                for (int j = 0; j < 8; j++)
                    mma_f16(acc[i][j], af[i], bf[j]);
        }
        __syncthreads();
    }

    // ---- epilogue ----
#pragma unroll
    for (int i = 0; i < 2; i++) {
        const int r0 = mt * 128 + wm * 32 + i * 16 + g;
        const int r1 = r0 + 8;
        const float sc0 = comp[r0 * 8 + zb];
        const float sc1 = comp[r1 * 8 + zb];
        __half* Cr0 = C + (size_t)r0 * 6144;
        __half* Cr1 = C + (size_t)r1 * 6144;
#pragma unroll
        for (int j = 0; j < 8; j++) {
            const int c = wn * 64 + j * 8 + 2 * t;
            *(__half2*)(Cr0 + c) =
                __floats2half2_rn(acc[i][j][0] * sc0, acc[i][j][1] * sc0);
            *(__half2*)(Cr1 + c) =
                __floats2half2_rn(acc[i][j][2] * sc1, acc[i][j][3] * sc1);
        }
    }
}

// ============================================================
// tf32 mma.sync GEMM (final projection only)
// ============================================================
#define AS_STRIDE 36

template<int MT, int NT, int NTHR>
__global__ __launch_bounds__(NTHR, 2)
void gemm_mma(const float* __restrict__ Abase, int lda, int a_blk,
              const float* __restrict__ W0, int ldb, int w_blk,
              float* __restrict__ C0, int ldc, int c_blk, int KC) {
    constexpr int BSS   = NT + 8;
    constexpr int A_BUF = MT * AS_STRIDE;
    constexpr int B_BUF = 32 * BSS;
    constexpr int STG   = A_BUF + B_BUF;
    constexpr int NWM   = MT / 32;
    constexpr int NWN   = (NTHR / 32) / NWM;
    constexpr int WNW   = NT / NWN;
    constexpr int JN    = WNW / 8;

    extern __shared__ __align__(16) float sm[];
    const uint32_t sbase = smem_u32(sm);

    const int tid  = threadIdx.x;
    const int wid  = tid >> 5;
    const int lane = tid & 31;
    const int wm   = wid % NWM;
    const int wn   = wid / NWM;
    const int g    = lane >> 2;
    const int t    = lane & 3;

    const int mt   = blockIdx.x;
    const int zb   = blockIdx.z;

    const float* W = W0 + (size_t)zb * w_blk;
    float* C = C0 + (size_t)zb * c_blk;
    const float* A = Abase + (size_t)mt * MT * lda + (size_t)zb * a_blk;

    const int a_m  = tid >> 3;
    const int a_k4 = tid & 7;

    float acc[2][JN][4];
#pragma unroll
    for (int i = 0; i < 2; i++)
#pragma unroll
        for (int j = 0; j < JN; j++)
#pragma unroll
            for (int c = 0; c < 4; c++) acc[i][j][c] = 0.f;

    auto issue_chunk = [&](int kc) {
        const int st = kc % 3;
        const uint32_t ad = sbase + (uint32_t)(st * STG) * 4;
        const uint32_t bd = ad + (uint32_t)A_BUF * 4;
        const int k0 = kc * 32;
#pragma unroll
        for (int p = 0; p < MT * 8 / NTHR; p++) {
            int m = a_m + p * (NTHR / 8);
            cp16(ad + (uint32_t)(m * AS_STRIDE + a_k4 * 4) * 4,
                 A + (size_t)m * lda + k0 + a_k4 * 4);
        }
#pragma unroll
        for (int p = 0; p < 32 * (NT / 4) / NTHR; p++) {
            int idx = p * NTHR + tid;
            int k   = idx / (NT / 4);
            int e4  = idx % (NT / 4);
            cp16(bd + (uint32_t)(k * BSS + e4 * 4) * 4,
                 W + (size_t)(k0 + k) * ldb + e4 * 4);
        }
    };

    issue_chunk(0);
    CP_COMMIT();
    if (KC > 1) { issue_chunk(1); CP_COMMIT(); }

    for (int kc = 0; kc < KC; kc++) {
        if (kc + 1 < KC) { CP_WAIT(1); } else { CP_WAIT(0); }
        __syncthreads();
        if (kc + 2 < KC) { issue_chunk(kc + 2); CP_COMMIT(); }

        const float* as = sm + (kc % 3) * STG;
        const float* bs = as + A_BUF;
#pragma unroll
        for (int ks = 0; ks < 4; ks++) {
            const int kk = ks * 8;
            uint32_t af[2][4];
#pragma unroll
            for (int i = 0; i < 2; i++) {
                const int r0 = wm * 32 + i * 16;
                af[i][0] = __float_as_uint(as[(r0 + g)     * AS_STRIDE + kk + t]);
                af[i][1] = __float_as_uint(as[(r0 + g + 8) * AS_STRIDE + kk + t]);
                af[i][2] = __float_as_uint(as[(r0 + g)     * AS_STRIDE + kk + t + 4]);
                af[i][3] = __float_as_uint(as[(r0 + g + 8) * AS_STRIDE + kk + t + 4]);
            }
            uint32_t bf[JN][2];
#pragma unroll
            for (int j = 0; j < JN; j++) {
                const int c = wn * WNW + j * 8 + g;
                bf[j][0] = __float_as_uint(bs[(kk + t)     * BSS + c]);
                bf[j][1] = __float_as_uint(bs[(kk + t + 4) * BSS + c]);
            }
#pragma unroll
            for (int i = 0; i < 2; i++)
#pragma unroll
                for (int j = 0; j < JN; j++)
                    mma_tf32(acc[i][j], af[i], bf[j]);
        }
    }

#pragma unroll
    for (int i = 0; i < 2; i++) {
        const int r0 = mt * MT + wm * 32 + i * 16 + g;
        const int r1 = r0 + 8;
        float* Cr0 = C + (size_t)r0 * ldc;
        float* Cr1 = C + (size_t)r1 * ldc;
#pragma unroll
        for (int j = 0; j < JN; j++) {
            const int c = wn * WNW + j * 8 + 2 * t;
            *(float2*)(Cr0 + c) = make_float2(acc[i][j][0], acc[i][j][1]);
            *(float2*)(Cr1 + c) = make_float2(acc[i][j][2], acc[i][j][3]);
        }
    }
}

// ============================================================
// Kernel C: register/shuffle block-attention (unchanged from R8)
// ============================================================
__global__ __launch_bounds__(384, 2)
void attn_kernel(float* __restrict__ out) {
    __shared__ float ss[12 * 64];

    const int t    = blockIdx.x;
    const int tid  = threadIdx.x;
    const int w    = tid >> 5;
    const int lane = tid & 31;
    const int n    = lane >> 2;
    const int p    = lane & 3;

    const size_t base = (size_t)t * 6144 + (size_t)n * 768 + w * 64 + p * 16;

    uint4 qa = *(const uint4*)(g_q + base);
    uint4 qb = *(const uint4*)(g_q + base + 8);
    uint4 ka = *(const uint4*)(g_k + base);
    uint4 kb = *(const uint4*)(g_k + base + 8);
    uint4 va = *(const uint4*)(g_v + base);
    uint4 vb = *(const uint4*)(g_v + base + 8);

    uint32_t kh[8] = {ka.x, ka.y, ka.z, ka.w, kb.x, kb.y, kb.z, kb.w};
    uint32_t vh[8] = {va.x, va.y, va.z, va.w, vb.x, vb.y, vb.z, vb.w};

    float qf[16];
    {
        const uint32_t qh[8] = {qa.x, qa.y, qa.z, qa.w, qb.x, qb.y, qb.z, qb.w};
#pragma unroll
        for (int r = 0; r < 8; r++) {
            float2 f = __half22float2(*(const __half2*)&qh[r]);
            qf[2 * r]     = f.x * 0.125f;
            qf[2 * r + 1] = f.y * 0.125f;
        }
    }

    float sc[8];
#pragma unroll
    for (int m = 0; m < 8; m++) {
        const int src = m * 4 + p;
        float a = 0.f;
#pragma unroll
        for (int r = 0; r < 8; r++) {
            uint32_t kk = __shfl_sync(0xffffffffu, kh[r], src);
            float2 f = __half22float2(*(const __half2*)&kk);
            a = fmaf(qf[2 * r], f.x, a);
            a = fmaf(qf[2 * r + 1], f.y, a);
        }
        sc[m] = a;
    }
#pragma unroll
    for (int o = 1; o <= 2; o <<= 1)
#pragma unroll
        for (int m = 0; m < 8; m++)
            sc[m] += __shfl_xor_sync(0xffffffffu, sc[m], o);

    float mx = sc[0];
#pragma unroll
    for (int m = 1; m < 8; m++) mx = fmaxf(mx, sc[m]);
    float den = 0.f;
#pragma unroll
    for (int m = 0; m < 8; m++) { sc[m] = __expf(sc[m] - mx); den += sc[m]; }
    const float inv = 1.0f / den;
#pragma unroll
    for (int m = 0; m < 8; m++) sc[m] *= inv;

    if (p == 0) {
#pragma unroll
        for (int m = 0; m < 8; m++) ss[w * 64 + n * 8 + m] = sc[m];
    }

    float of[16];
#pragma unroll
    for (int r = 0; r < 16; r++) of[r] = 0.f;
#pragma unroll
    for (int m = 0; m < 8; m++) {
        const int src = m * 4 + p;
        const float a = sc[m];
#pragma unroll
        for (int r = 0; r < 8; r++) {
            uint32_t vv = __shfl_sync(0xffffffffu, vh[r], src);
            float2 f = __half22float2(*(const __half2*)&vv);
            of[2 * r]     = fmaf(a, f.x, of[2 * r]);
            of[2 * r + 1] = fmaf(a, f.y, of[2 * r + 1]);
        }
    }
    float* dst = g_o + base;
#pragma unroll
    for (int r = 0; r < 4; r++) {
        float4 o;
        o.x = __uint_as_float(tf32r(of[4 * r + 0]));
        o.y = __uint_as_float(tf32r(of[4 * r + 1]));
        o.z = __uint_as_float(tf32r(of[4 * r + 2]));
        o.w = __uint_as_float(tf32r(of[4 * r + 3]));
        *(float4*)(dst + 4 * r) = o;
    }

    __syncthreads();
    if (tid < 64) {
        float sum = 0.f;
#pragma unroll
        for (int h = 0; h < 12; h++) sum += ss[h * 64 + tid];
        out[4194304 + (size_t)t * 64 + tid] = sum * (1.0f / 12.0f);
    }
}

// ============================================================
// launch
// ============================================================
#define SMEM_FIN (3 * (64 * AS_STRIDE + 32 * (128 + 8)) * 4)  // 79872

extern "C" void kernel_launch(void* const* d_in, const int* in_sizes, int n_in,
                              void* d_out, int out_size) {
    const float* x  = (const float*)d_in[0];
    const float* wc = (const float*)d_in[1];
    const float* wq = (const float*)d_in[2];
    const float* wk = (const float*)d_in[3];
    const float* wv = (const float*)d_in[4];
    const float* wf = (const float*)d_in[5];
    float* out = (float*)d_out;

    __half *gq, *gk, *gv, *gxh;
    __half2 *gwqh, *gwkh, *gwvh;
    float *go, *gc, *gwf;
    cudaGetSymbolAddress((void**)&gq, g_q);
    cudaGetSymbolAddress((void**)&gk, g_k);
    cudaGetSymbolAddress((void**)&gv, g_v);
    cudaGetSymbolAddress((void**)&go, g_o);
    cudaGetSymbolAddress((void**)&gc, g_comp);
    cudaGetSymbolAddress((void**)&gxh, g_xh);
    cudaGetSymbolAddress((void**)&gwqh, g_wqh);
    cudaGetSymbolAddress((void**)&gwkh, g_wkh);
    cudaGetSymbolAddress((void**)&gwvh, g_wvh);
    cudaGetSymbolAddress((void**)&gwf, g_wfr);

    cudaFuncSetAttribute(qkv16_kernel,
                         cudaFuncAttributeMaxDynamicSharedMemorySize, SMEM_Q16);
    cudaFuncSetAttribute(gemm_mma<64, 128, 256>,
                         cudaFuncAttributeMaxDynamicSharedMemorySize, SMEM_FIN);

    // prep: x fp16, weight fp16 packs, wf tf32 round — one launch
    prep_kernel<<<NPREP / 256, 256>>>(x, wq, wk, wv, wf);

    // A: gating (full-precision x)
    comp_kernel<<<512, 256>>>(x, wc);

    // B: fp16 QKV GEMMs. 18 = 3 mats x 6 col-tiles of 128.
    dim3 gB(32, 18, 8);
    qkv16_kernel<<<gB, 256, SMEM_Q16>>>(
        gxh, (const uint32_t*)gwqh, (const uint32_t*)gwkh,
        (const uint32_t*)gwvh, gq, gk, gv, gc);

    // C: register/shuffle attention + score_mean
    attn_kernel<<<TOK, 384>>>(out);

    // D: final tf32 GEMM. K=768 -> KC=24, m-tile 64.
    dim3 gD(64, 1, 8);
    gemm_mma<64, 128, 256><<<gD, 256, SMEM_FIN>>>(
        go, 6144, 768,
        gwf, 128, 98304,
        out, 1024, 128,
        24);
}

// round 10
// speedup vs baseline: 1.6016x; 1.1428x over previous
#include <cuda_runtime.h>
#include <cuda_fp16.h>
#include <cstdint>

#define TOK 4096
#define QKV_ELEMS ((size_t)TOK * 6144)

// ---- scratch ----
__device__ float  g_comp[TOK * 8];
__device__ __half g_q[QKV_ELEMS];
__device__ __half g_k[QKV_ELEMS];
__device__ __half g_v[QKV_ELEMS];
__device__ __half g_oh[QKV_ELEMS];        // attention out, fp16
__device__ __half g_xh[4194304];          // x as fp16 [4096][1024]
__device__ __half2 g_wqh[393216];         // packed [8][64 kp][768 e]
__device__ __half2 g_wkh[393216];
__device__ __half2 g_wvh[393216];
__device__ __half2 g_wfh[393216];         // packed [8][384 kp][128 e]

// ============================================================
// helpers
// ============================================================
__device__ __forceinline__ uint32_t smem_u32(const void* p) {
    uint32_t a;
    asm("{ .reg .u64 t; cvta.to.shared.u64 t, %1; cvt.u32.u64 %0, t; }"
        : "=r"(a) : "l"(p));
    return a;
}
__device__ __forceinline__ void cp16(uint32_t dst, const void* src) {
    asm volatile("cp.async.ca.shared.global [%0], [%1], 16;"
                 :: "r"(dst), "l"(src));
}
#define CP_COMMIT() asm volatile("cp.async.commit_group;" ::: "memory")
#define CP_WAIT(n)  asm volatile("cp.async.wait_group %0;" :: "n"(n) : "memory")

__device__ __forceinline__ void mma_f16(float* c, const uint32_t* a,
                                        const uint32_t* b) {
    asm volatile(
        "mma.sync.aligned.m16n8k16.row.col.f32.f16.f16.f32 "
        "{%0,%1,%2,%3}, {%4,%5,%6,%7}, {%8,%9}, {%0,%1,%2,%3};"
        : "+f"(c[0]), "+f"(c[1]), "+f"(c[2]), "+f"(c[3])
        : "r"(a[0]), "r"(a[1]), "r"(a[2]), "r"(a[3]), "r"(b[0]), "r"(b[1]));
}

// ============================================================
// prep: x->fp16 | wq/wk/wv/wf fp16-pack (k-pairs), one launch
// ============================================================
#define NX4 1048576      // x float4 units
#define NWP 98304        // pack units per weight
#define NPREP (NX4 + 4 * NWP)   // 1441792

__global__ void prep_kernel(const float* __restrict__ x,
                            const float* __restrict__ wq,
                            const float* __restrict__ wk,
                            const float* __restrict__ wv,
                            const float* __restrict__ wf) {
    int u = blockIdx.x * blockDim.x + threadIdx.x;
    if (u >= NPREP) return;
    if (u < NX4) {
        float4 v = ((const float4*)x)[u];
        __half2 h0 = __floats2half2_rn(v.x, v.y);
        __half2 h1 = __floats2half2_rn(v.z, v.w);
        *(uint2*)&g_xh[(size_t)u * 4] =
            make_uint2(*(uint32_t*)&h0, *(uint32_t*)&h1);
        return;
    }
    u -= NX4;
    const float* w; __half2* o;
    int ldw, kps;   // row stride (e-dim), kp count
    if (u < NWP)            { w = wq; o = g_wqh; ldw = 768; kps = 64; }
    else if (u < 2 * NWP)   { w = wk; o = g_wkh; ldw = 768; kps = 64; u -= NWP; }
    else if (u < 3 * NWP)   { w = wv; o = g_wvh; ldw = 768; kps = 64; u -= 2 * NWP; }
    else                    { w = wf; o = g_wfh; ldw = 128; kps = 384; u -= 3 * NWP; }
    const int ne4 = ldw / 4;
    int e4 = u % ne4;
    int kp = (u / ne4) % kps;
    int nb = u / (ne4 * kps);
    const float* lo = w + (size_t)nb * 98304 + (size_t)(2 * kp) * ldw + e4 * 4;
    float4 l = *(const float4*)lo;
    float4 h = *(const float4*)(lo + ldw);
    __half2 p[4];
    p[0] = __halves2half2(__float2half_rn(l.x), __float2half_rn(h.x));
    p[1] = __halves2half2(__float2half_rn(l.y), __float2half_rn(h.y));
    p[2] = __halves2half2(__float2half_rn(l.z), __float2half_rn(h.z));
    p[3] = __halves2half2(__float2half_rn(l.w), __float2half_rn(h.w));
    *(uint4*)&o[(size_t)nb * 49152 + (size_t)kp * ldw + e4 * 4] = *(uint4*)p;
}

// ============================================================
// Kernel A: competition gating
// ============================================================
__global__ void comp_kernel(const float* __restrict__ x,
                            const float* __restrict__ wc) {
    int gtid = blockIdx.x * blockDim.x + threadIdx.x;
    int t    = gtid >> 5;
    int lane = gtid & 31;
    if (t >= TOK) return;
    const float* xr = x + (size_t)t * 1024;

    float logit[8];
#pragma unroll
    for (int n = 0; n < 8; n++) {
        const float* xb = xr + n * 128;
        const float* wb = wc + n * 128;
        float p = xb[lane]      * wb[lane]
                + xb[lane + 32] * wb[lane + 32]
                + xb[lane + 64] * wb[lane + 64]
                + xb[lane + 96] * wb[lane + 96];
#pragma unroll
        for (int o = 16; o > 0; o >>= 1) p += __shfl_xor_sync(0xffffffffu, p, o);
        logit[n] = p;
    }
    float mx = logit[0];
#pragma unroll
    for (int n = 1; n < 8; n++) mx = fmaxf(mx, logit[n]);
    float s = 0.f, ev = 0.f;
#pragma unroll
    for (int n = 0; n < 8; n++) {
        float e = __expf(logit[n] - mx);
        s += e;
        if (lane == n) ev = e;
    }
    if (lane < 8) g_comp[t * 8 + lane] = ev / s;
}

// ============================================================
// fp16 QKV GEMM (unchanged from R9)
// ============================================================
#define QA_W 2560
#define QB_W 2176
#define QSTG_W (QA_W + QB_W)
#define SMEM_Q16 (3 * QSTG_W * 4)  // 56832

__global__ __launch_bounds__(256, 2)
void qkv16_kernel(const __half* __restrict__ Xh,
                  const uint32_t* __restrict__ WQ,
                  const uint32_t* __restrict__ WK,
                  const uint32_t* __restrict__ WV,
                  __half* __restrict__ CQ, __half* __restrict__ CK,
                  __half* __restrict__ CV,
                  const float* __restrict__ comp) {
    extern __shared__ __align__(16) uint32_t smw[];
    const uint32_t sbase = smem_u32(smw);

    const int tid  = threadIdx.x;
    const int wid  = tid >> 5;
    const int lane = tid & 31;
    const int wm   = wid & 3;
    const int wn   = wid >> 2;
    const int g    = lane >> 2;
    const int t    = lane & 3;

    const int mt   = blockIdx.x;
    const int yy   = blockIdx.y;
    const int zb   = blockIdx.z;
    const int mat  = yy / 6;
    const int col0 = (yy % 6) * 128;

    const uint32_t* Wh = (mat == 0 ? WQ : (mat == 1 ? WK : WV)) +
                         (size_t)zb * 49152 + col0;
    __half* C = (mat == 0 ? CQ : (mat == 1 ? CK : CV)) +
                (size_t)zb * 768 + col0;
    const __half* Ah = Xh + (size_t)(mt * 128) * 1024 + zb * 128;

    float acc[2][8][4];
#pragma unroll
    for (int i = 0; i < 2; i++)
#pragma unroll
        for (int j = 0; j < 8; j++)
#pragma unroll
            for (int c = 0; c < 4; c++) acc[i][j][c] = 0.f;

    auto issue_chunk = [&](int kc) {
        const int st = kc % 3;
        const uint32_t ad = sbase + (uint32_t)(st * QSTG_W) * 4;
        const uint32_t bd = ad + QA_W * 4;
        const int k0h = kc * 32;
#pragma unroll
        for (int p = 0; p < 2; p++) {
            int idx = p * 256 + tid;
            int r = idx >> 2, c16 = idx & 3;
            cp16(ad + (uint32_t)(r * 20 + c16 * 4) * 4,
                 Ah + (size_t)r * 1024 + k0h + c16 * 8);
        }
#pragma unroll
        for (int p = 0; p < 2; p++) {
            int idx = p * 256 + tid;
            int kpl = idx >> 5, c = idx & 31;
            cp16(bd + (uint32_t)(kpl * 136 + c * 4) * 4,
                 Wh + (size_t)(kc * 16 + kpl) * 768 + c * 4);
        }
    };

    issue_chunk(0);
    CP_COMMIT();
    issue_chunk(1);
    CP_COMMIT();

    for (int kc = 0; kc < 4; kc++) {
        if (kc + 1 < 4) { CP_WAIT(1); } else { CP_WAIT(0); }
        __syncthreads();
        if (kc + 2 < 4) { issue_chunk(kc + 2); CP_COMMIT(); }

        const uint32_t* aw = smw + (kc % 3) * QSTG_W;
        const uint32_t* bw = aw + QA_W;
#pragma unroll
        for (int ks = 0; ks < 2; ks++) {
            uint32_t af[2][4];
#pragma unroll
            for (int i = 0; i < 2; i++) {
                const int r0 = wm * 32 + i * 16;
                af[i][0] = aw[(r0 + g)     * 20 + ks * 8 + t];
                af[i][1] = aw[(r0 + g + 8) * 20 + ks * 8 + t];
                af[i][2] = aw[(r0 + g)     * 20 + ks * 8 + t + 4];
                af[i][3] = aw[(r0 + g + 8) * 20 + ks * 8 + t + 4];
            }
            uint32_t bf[8][2];
#pragma unroll
            for (int j = 0; j < 8; j++) {
                const int c = wn * 64 + j * 8 + g;
                bf[j][0] = bw[(ks * 8 + t)     * 136 + c];
                bf[j][1] = bw[(ks * 8 + 4 + t) * 136 + c];
            }
#pragma unroll
            for (int i = 0; i < 2; i++)
#pragma unroll
                for (int j = 0; j < 8; j++)
                    mma_f16(acc[i][j], af[i], bf[j]);
        }
        __syncthreads();
    }

#pragma unroll
    for (int i = 0; i < 2; i++) {
        const int r0 = mt * 128 + wm * 32 + i * 16 + g;
        const int r1 = r0 + 8;
        const float sc0 = comp[r0 * 8 + zb];
        const float sc1 = comp[r1 * 8 + zb];
        __half* Cr0 = C + (size_t)r0 * 6144;
        __half* Cr1 = C + (size_t)r1 * 6144;
#pragma unroll
        for (int j = 0; j < 8; j++) {
            const int c = wn * 64 + j * 8 + 2 * t;
            *(__half2*)(Cr0 + c) =
                __floats2half2_rn(acc[i][j][0] * sc0, acc[i][j][1] * sc0);
            *(__half2*)(Cr1 + c) =
                __floats2half2_rn(acc[i][j][2] * sc1, acc[i][j][3] * sc1);
        }
    }
}

// ============================================================
// fp16 final GEMM: per (mt, zb) C[64x128] = O[64x768] @ Wf[768x128]
//   8 warps 2x4 (warp tile 32x32), 3-stage, k-chunk 32, KC=24.
// ============================================================
#define FA_W 1280            // A words per stage (64*20)
#define FB_W 2176            // B words per stage (16*136)
#define FSTG_W (FA_W + FB_W) // 3456
#define SMEM_F16 (3 * FSTG_W * 4)  // 41472

__global__ __launch_bounds__(256, 2)
void fin16_kernel(const __half* __restrict__ Oh,
                  const uint32_t* __restrict__ WF,
                  float* __restrict__ out) {
    extern __shared__ __align__(16) uint32_t smw[];
    const uint32_t sbase = smem_u32(smw);

    const int tid  = threadIdx.x;
    const int wid  = tid >> 5;
    const int lane = tid & 31;
    const int wm   = wid & 1;
    const int wn   = wid >> 1;
    const int g    = lane >> 2;
    const int t    = lane & 3;

    const int mt = blockIdx.x;
    const int zb = blockIdx.z;

    const uint32_t* Wh = WF + (size_t)zb * 49152;
    const __half* Ah = Oh + (size_t)(mt * 64) * 6144 + zb * 768;
    float* C = out + (size_t)zb * 128;

    float acc[2][4][4];
#pragma unroll
    for (int i = 0; i < 2; i++)
#pragma unroll
        for (int j = 0; j < 4; j++)
#pragma unroll
            for (int c = 0; c < 4; c++) acc[i][j][c] = 0.f;

    auto issue_chunk = [&](int kc) {
        const int st = kc % 3;
        const uint32_t ad = sbase + (uint32_t)(st * FSTG_W) * 4;
        const uint32_t bd = ad + FA_W * 4;
        // A: 64 rows x 32 halfs = 256 cp16, 1 per thread
        {
            int r = tid >> 2, c16 = tid & 3;
            cp16(ad + (uint32_t)(r * 20 + c16 * 4) * 4,
                 Ah + (size_t)r * 6144 + kc * 32 + c16 * 8);
        }
        // B: 16 kp x 128 half2 = 512 cp16, 2 per thread
#pragma unroll
        for (int p = 0; p < 2; p++) {
            int idx = p * 256 + tid;
            int kpl = idx >> 5, c = idx & 31;
            cp16(bd + (uint32_t)(kpl * 136 + c * 4) * 4,
                 Wh + (size_t)(kc * 16 + kpl) * 128 + c * 4);
        }
    };

    issue_chunk(0);
    CP_COMMIT();
    issue_chunk(1);
    CP_COMMIT();

    for (int kc = 0; kc < 24; kc++) {
        if (kc + 1 < 24) { CP_WAIT(1); } else { CP_WAIT(0); }
        __syncthreads();
        if (kc + 2 < 24) { issue_chunk(kc + 2); CP_COMMIT(); }

        const uint32_t* aw = smw + (kc % 3) * FSTG_W;
        const uint32_t* bw = aw + FA_W;
#pragma unroll
        for (int ks = 0; ks < 2; ks++) {
            uint32_t af[2][4];
#pragma unroll
            for (int i = 0; i < 2; i++) {
                const int r0 = wm * 32 + i * 16;
                af[i][0] = aw[(r0 + g)     * 20 + ks * 8 + t];
                af[i][1] = aw[(r0 + g + 8) * 20 + ks * 8 + t];
                af[i][2] = aw[(r0 + g)     * 20 + ks * 8 + t + 4];
                af[i][3] = aw[(r0 + g + 8) * 20 + ks * 8 + t + 4];
            }
            uint32_t bf[4][2];
#pragma unroll
            for (int j = 0; j < 4; j++) {
                const int c = wn * 32 + j * 8 + g;
                bf[j][0] = bw[(ks * 8 + t)     * 136 + c];
                bf[j][1] = bw[(ks * 8 + 4 + t) * 136 + c];
            }
#pragma unroll
            for (int i = 0; i < 2; i++)
#pragma unroll
                for (int j = 0; j < 4; j++)
                    mma_f16(acc[i][j], af[i], bf[j]);
        }
        __syncthreads();
    }

#pragma unroll
    for (int i = 0; i < 2; i++) {
        const int r0 = mt * 64 + wm * 32 + i * 16 + g;
        const int r1 = r0 + 8;
        float* Cr0 = C + (size_t)r0 * 1024;
        float* Cr1 = C + (size_t)r1 * 1024;
#pragma unroll
        for (int j = 0; j < 4; j++) {
            const int c = wn * 32 + j * 8 + 2 * t;
            *(float2*)(Cr0 + c) = make_float2(acc[i][j][0], acc[i][j][1]);
            *(float2*)(Cr1 + c) = make_float2(acc[i][j][2], acc[i][j][3]);
        }
    }
}

// ============================================================
// Kernel C: register/shuffle block-attention; fp16 output
// ============================================================
__global__ __launch_bounds__(384, 2)
void attn_kernel(float* __restrict__ out) {
    __shared__ float ss[12 * 64];

    const int t    = blockIdx.x;
    const int tid  = threadIdx.x;
    const int w    = tid >> 5;
    const int lane = tid & 31;
    const int n    = lane >> 2;
    const int p    = lane & 3;

    const size_t base = (size_t)t * 6144 + (size_t)n * 768 + w * 64 + p * 16;

    uint4 qa = *(const uint4*)(g_q + base);
    uint4 qb = *(const uint4*)(g_q + base + 8);
    uint4 ka = *(const uint4*)(g_k + base);
    uint4 kb = *(const uint4*)(g_k + base + 8);
    uint4 va = *(const uint4*)(g_v + base);
    uint4 vb = *(const uint4*)(g_v + base + 8);

    uint32_t kh[8] = {ka.x, ka.y, ka.z, ka.w, kb.x, kb.y, kb.z, kb.w};
    uint32_t vh[8] = {va.x, va.y, va.z, va.w, vb.x, vb.y, vb.z, vb.w};

    float qf[16];
    {
        const uint32_t qh[8] = {qa.x, qa.y, qa.z, qa.w, qb.x, qb.y, qb.z, qb.w};
#pragma unroll
        for (int r = 0; r < 8; r++) {
            float2 f = __half22float2(*(const __half2*)&qh[r]);
            qf[2 * r]     = f.x * 0.125f;
            qf[2 * r + 1] = f.y * 0.125f;
        }
    }

    float sc[8];
#pragma unroll
    for (int m = 0; m < 8; m++) {
        const int src = m * 4 + p;
        float a = 0.f;
#pragma unroll
        for (int r = 0; r < 8; r++) {
            uint32_t kk = __shfl_sync(0xffffffffu, kh[r], src);
            float2 f = __half22float2(*(const __half2*)&kk);
            a = fmaf(qf[2 * r], f.x, a);
            a = fmaf(qf[2 * r + 1], f.y, a);
        }
        sc[m] = a;
    }
#pragma unroll
    for (int o = 1; o <= 2; o <<= 1)
#pragma unroll
        for (int m = 0; m < 8; m++)
            sc[m] += __shfl_xor_sync(0xffffffffu, sc[m], o);

    float mx = sc[0];
#pragma unroll
    for (int m = 1; m < 8; m++) mx = fmaxf(mx, sc[m]);
    float den = 0.f;
#pragma unroll
    for (int m = 0; m < 8; m++) { sc[m] = __expf(sc[m] - mx); den += sc[m]; }
    const float inv = 1.0f / den;
#pragma unroll
    for (int m = 0; m < 8; m++) sc[m] *= inv;

    if (p == 0) {
#pragma unroll
        for (int m = 0; m < 8; m++) ss[w * 64 + n * 8 + m] = sc[m];
    }

    float of[16];
#pragma unroll
    for (int r = 0; r < 16; r++) of[r] = 0.f;
#pragma unroll
    for (int m = 0; m < 8; m++) {
        const int src = m * 4 + p;
        const float a = sc[m];
#pragma unroll
        for (int r = 0; r < 8; r++) {
            uint32_t vv = __shfl_sync(0xffffffffu, vh[r], src);
            float2 f = __half22float2(*(const __half2*)&vv);
            of[2 * r]     = fmaf(a, f.x, of[2 * r]);
            of[2 * r + 1] = fmaf(a, f.y, of[2 * r + 1]);
        }
    }
    // fp16 store: 16 halfs = 2 x uint4
    __half2 oh[8];
#pragma unroll
    for (int r = 0; r < 8; r++)
        oh[r] = __floats2half2_rn(of[2 * r], of[2 * r + 1]);
    __half* dst = g_oh + base;
    *(uint4*)dst       = *(uint4*)&oh[0];
    *(uint4*)(dst + 8) = *(uint4*)&oh[4];

    __syncthreads();
    if (tid < 64) {
        float sum = 0.f;
#pragma unroll
        for (int h = 0; h < 12; h++) sum += ss[h * 64 + tid];
        out[4194304 + (size_t)t * 64 + tid] = sum * (1.0f / 12.0f);
    }
}

// ============================================================
// launch
// ============================================================
extern "C" void kernel_launch(void* const* d_in, const int* in_sizes, int n_in,
                              void* d_out, int out_size) {
    const float* x  = (const float*)d_in[0];
    const float* wc = (const float*)d_in[1];
    const float* wq = (const float*)d_in[2];
    const float* wk = (const float*)d_in[3];
    const float* wv = (const float*)d_in[4];
    const float* wf = (const float*)d_in[5];
    float* out = (float*)d_out;

    __half *gq, *gk, *gv, *goh, *gxh;
    __half2 *gwqh, *gwkh, *gwvh, *gwfh;
    float *gc;
    cudaGetSymbolAddress((void**)&gq, g_q);
    cudaGetSymbolAddress((void**)&gk, g_k);
    cudaGetSymbolAddress((void**)&gv, g_v);
    cudaGetSymbolAddress((void**)&goh, g_oh);
    cudaGetSymbolAddress((void**)&gc, g_comp);
    cudaGetSymbolAddress((void**)&gxh, g_xh);
    cudaGetSymbolAddress((void**)&gwqh, g_wqh);
    cudaGetSymbolAddress((void**)&gwkh, g_wkh);
    cudaGetSymbolAddress((void**)&gwvh, g_wvh);
    cudaGetSymbolAddress((void**)&gwfh, g_wfh);

    cudaFuncSetAttribute(qkv16_kernel,
                         cudaFuncAttributeMaxDynamicSharedMemorySize, SMEM_Q16);
    cudaFuncSetAttribute(fin16_kernel,
                         cudaFuncAttributeMaxDynamicSharedMemorySize, SMEM_F16);

    // prep: x fp16, all 4 weight fp16 packs — one launch
    prep_kernel<<<NPREP / 256, 256>>>(x, wq, wk, wv, wf);

    // A: gating (full-precision x)
    comp_kernel<<<512, 256>>>(x, wc);

    // B: fp16 QKV GEMMs. 18 = 3 mats x 6 col-tiles of 128.
    dim3 gB(32, 18, 8);
    qkv16_kernel<<<gB, 256, SMEM_Q16>>>(
        gxh, (const uint32_t*)gwqh, (const uint32_t*)gwkh,
        (const uint32_t*)gwvh, gq, gk, gv, gc);

    // C: register/shuffle attention + score_mean (fp16 out)
    attn_kernel<<<TOK, 384>>>(out);

    // D: fp16 final GEMM. grid (64 m-tiles, 1, 8 blocks).
    dim3 gD(64, 1, 8);
    fin16_kernel<<<gD, 256, SMEM_F16>>>(goh, (const uint32_t*)gwfh, out);
}

// round 11
// speedup vs baseline: 1.6949x; 1.0582x over previous
#include <cuda_runtime.h>
#include <cuda_fp16.h>
#include <cstdint>

#define TOK 4096
#define QKV_ELEMS ((size_t)TOK * 6144)

// ---- scratch ----
__device__ float  g_comp[TOK * 8];
__device__ __half g_q[QKV_ELEMS];
__device__ __half g_k[QKV_ELEMS];
__device__ __half g_v[QKV_ELEMS];
__device__ __half g_oh[QKV_ELEMS];        // attention out, fp16
__device__ __half g_xh[4194304];          // x as fp16 [4096][1024]
__device__ __half2 g_wqh[393216];         // packed [8][64 kp][768 e]
__device__ __half2 g_wkh[393216];
__device__ __half2 g_wvh[393216];
__device__ __half2 g_wfh[393216];         // packed [8][384 kp][128 e]

// ============================================================
// helpers
// ============================================================
__device__ __forceinline__ uint32_t smem_u32(const void* p) {
    uint32_t a;
    asm("{ .reg .u64 t; cvta.to.shared.u64 t, %1; cvt.u32.u64 %0, t; }"
        : "=r"(a) : "l"(p));
    return a;
}
__device__ __forceinline__ void cp16(uint32_t dst, const void* src) {
    asm volatile("cp.async.ca.shared.global [%0], [%1], 16;"
                 :: "r"(dst), "l"(src));
}
#define CP_COMMIT() asm volatile("cp.async.commit_group;" ::: "memory")
#define CP_WAIT(n)  asm volatile("cp.async.wait_group %0;" :: "n"(n) : "memory")

__device__ __forceinline__ void mma_f16(float* c, const uint32_t* a,
                                        const uint32_t* b) {
    asm volatile(
        "mma.sync.aligned.m16n8k16.row.col.f32.f16.f16.f32 "
        "{%0,%1,%2,%3}, {%4,%5,%6,%7}, {%8,%9}, {%0,%1,%2,%3};"
        : "+f"(c[0]), "+f"(c[1]), "+f"(c[2]), "+f"(c[3])
        : "r"(a[0]), "r"(a[1]), "r"(a[2]), "r"(a[3]), "r"(b[0]), "r"(b[1]));
}
__device__ __forceinline__ void ldm_x4(uint32_t* r, uint32_t addr) {
    asm volatile(
        "ldmatrix.sync.aligned.m8n8.x4.shared.b16 {%0,%1,%2,%3}, [%4];"
        : "=r"(r[0]), "=r"(r[1]), "=r"(r[2]), "=r"(r[3]) : "r"(addr));
}

// ============================================================
// fused prep + gating:
//   blocks [0, PREP_BLKS): x->fp16 | wq/wk/wv/wf fp16 k-pair pack
//   blocks [PREP_BLKS, PREP_BLKS+512): competition gating
// ============================================================
#define NX4 1048576      // x float4 units
#define NWP 98304        // pack units per weight
#define NPREP (NX4 + 4 * NWP)   // 1441792
#define PREP_BLKS (NPREP / 256) // 5632
#define TOTAL_BLKS (PREP_BLKS + 512)

__global__ void prep_kernel(const float* __restrict__ x,
                            const float* __restrict__ wq,
                            const float* __restrict__ wk,
                            const float* __restrict__ wv,
                            const float* __restrict__ wf,
                            const float* __restrict__ wc) {
    if (blockIdx.x >= PREP_BLKS) {
        // ---- gating ----
        int gtid = (blockIdx.x - PREP_BLKS) * 256 + threadIdx.x;
        int t    = gtid >> 5;
        int lane = gtid & 31;
        const float* xr = x + (size_t)t * 1024;

        float logit[8];
#pragma unroll
        for (int n = 0; n < 8; n++) {
            const float* xb = xr + n * 128;
            const float* wb = wc + n * 128;
            float p = xb[lane]      * wb[lane]
                    + xb[lane + 32] * wb[lane + 32]
                    + xb[lane + 64] * wb[lane + 64]
                    + xb[lane + 96] * wb[lane + 96];
#pragma unroll
            for (int o = 16; o > 0; o >>= 1)
                p += __shfl_xor_sync(0xffffffffu, p, o);
            logit[n] = p;
        }
        float mx = logit[0];
#pragma unroll
        for (int n = 1; n < 8; n++) mx = fmaxf(mx, logit[n]);
        float s = 0.f, ev = 0.f;
#pragma unroll
        for (int n = 0; n < 8; n++) {
            float e = __expf(logit[n] - mx);
            s += e;
            if (lane == n) ev = e;
        }
        if (lane < 8) g_comp[t * 8 + lane] = ev / s;
        return;
    }

    int u = blockIdx.x * 256 + threadIdx.x;
    if (u < NX4) {
        float4 v = ((const float4*)x)[u];
        __half2 h0 = __floats2half2_rn(v.x, v.y);
        __half2 h1 = __floats2half2_rn(v.z, v.w);
        *(uint2*)&g_xh[(size_t)u * 4] =
            make_uint2(*(uint32_t*)&h0, *(uint32_t*)&h1);
        return;
    }
    u -= NX4;
    const float* w; __half2* o;
    int ldw, kps;
    if (u < NWP)            { w = wq; o = g_wqh; ldw = 768; kps = 64; }
    else if (u < 2 * NWP)   { w = wk; o = g_wkh; ldw = 768; kps = 64; u -= NWP; }
    else if (u < 3 * NWP)   { w = wv; o = g_wvh; ldw = 768; kps = 64; u -= 2 * NWP; }
    else                    { w = wf; o = g_wfh; ldw = 128; kps = 384; u -= 3 * NWP; }
    const int ne4 = ldw / 4;
    int e4 = u % ne4;
    int kp = (u / ne4) % kps;
    int nb = u / (ne4 * kps);
    const float* lo = w + (size_t)nb * 98304 + (size_t)(2 * kp) * ldw + e4 * 4;
    float4 l = *(const float4*)lo;
    float4 h = *(const float4*)(lo + ldw);
    __half2 p[4];
    p[0] = __halves2half2(__float2half_rn(l.x), __float2half_rn(h.x));
    p[1] = __halves2half2(__float2half_rn(l.y), __float2half_rn(h.y));
    p[2] = __halves2half2(__float2half_rn(l.z), __float2half_rn(h.z));
    p[3] = __halves2half2(__float2half_rn(l.w), __float2half_rn(h.w));
    *(uint4*)&o[(size_t)nb * 49152 + (size_t)kp * ldw + e4 * 4] = *(uint4*)p;
}

// ============================================================
// fp16 QKV GEMM: ldmatrix A-frags, single sync per chunk
// ============================================================
#define QA_W 2560
#define QB_W 2176
#define QSTG_W (QA_W + QB_W)
#define SMEM_Q16 (3 * QSTG_W * 4)  // 56832

__global__ __launch_bounds__(256, 2)
void qkv16_kernel(const __half* __restrict__ Xh,
                  const uint32_t* __restrict__ WQ,
                  const uint32_t* __restrict__ WK,
                  const uint32_t* __restrict__ WV,
                  __half* __restrict__ CQ, __half* __restrict__ CK,
                  __half* __restrict__ CV,
                  const float* __restrict__ comp) {
    extern __shared__ __align__(16) uint32_t smw[];
    const uint32_t sbase = smem_u32(smw);

    const int tid  = threadIdx.x;
    const int wid  = tid >> 5;
    const int lane = tid & 31;
    const int wm   = wid & 3;
    const int wn   = wid >> 2;
    const int g    = lane >> 2;
    const int t    = lane & 3;

    const int mt   = blockIdx.x;
    const int yy   = blockIdx.y;
    const int zb   = blockIdx.z;
    const int mat  = yy / 6;
    const int col0 = (yy % 6) * 128;

    const uint32_t* Wh = (mat == 0 ? WQ : (mat == 1 ? WK : WV)) +
                         (size_t)zb * 49152 + col0;
    __half* C = (mat == 0 ? CQ : (mat == 1 ? CK : CV)) +
                (size_t)zb * 768 + col0;
    const __half* Ah = Xh + (size_t)(mt * 128) * 1024 + zb * 128;

    // ldmatrix per-lane A address base (bytes within stage)
    const uint32_t a_lm = (uint32_t)((wm * 32 + (lane & 15)) * 80 +
                                     (lane >> 4) * 16);

    float acc[2][8][4];
#pragma unroll
    for (int i = 0; i < 2; i++)
#pragma unroll
        for (int j = 0; j < 8; j++)
#pragma unroll
            for (int c = 0; c < 4; c++) acc[i][j][c] = 0.f;

    auto issue_chunk = [&](int kc) {
        const int st = kc % 3;
        const uint32_t ad = sbase + (uint32_t)(st * QSTG_W) * 4;
        const uint32_t bd = ad + QA_W * 4;
        const int k0h = kc * 32;
#pragma unroll
        for (int p = 0; p < 2; p++) {
            int idx = p * 256 + tid;
            int r = idx >> 2, c16 = idx & 3;
            cp16(ad + (uint32_t)(r * 20 + c16 * 4) * 4,
                 Ah + (size_t)r * 1024 + k0h + c16 * 8);
        }
#pragma unroll
        for (int p = 0; p < 2; p++) {
            int idx = p * 256 + tid;
            int kpl = idx >> 5, c = idx & 31;
            cp16(bd + (uint32_t)(kpl * 136 + c * 4) * 4,
                 Wh + (size_t)(kc * 16 + kpl) * 768 + c * 4);
        }
    };

    issue_chunk(0);
    CP_COMMIT();
    issue_chunk(1);
    CP_COMMIT();

    for (int kc = 0; kc < 4; kc++) {
        if (kc + 1 < 4) { CP_WAIT(1); } else { CP_WAIT(0); }
        __syncthreads();
        if (kc + 2 < 4) { issue_chunk(kc + 2); CP_COMMIT(); }

        const uint32_t* bw = smw + (kc % 3) * QSTG_W + QA_W;
        const uint32_t a_stage = sbase + (uint32_t)((kc % 3) * QSTG_W) * 4 + a_lm;
#pragma unroll
        for (int ks = 0; ks < 2; ks++) {
            uint32_t af[2][4];
#pragma unroll
            for (int i = 0; i < 2; i++)
                ldm_x4(af[i], a_stage + i * 16 * 80 + ks * 32);
            uint32_t bf[8][2];
#pragma unroll
            for (int j = 0; j < 8; j++) {
                const int c = wn * 64 + j * 8 + g;
                bf[j][0] = bw[(ks * 8 + t)     * 136 + c];
                bf[j][1] = bw[(ks * 8 + 4 + t) * 136 + c];
            }
#pragma unroll
            for (int i = 0; i < 2; i++)
#pragma unroll
                for (int j = 0; j < 8; j++)
                    mma_f16(acc[i][j], af[i], bf[j]);
        }
    }

#pragma unroll
    for (int i = 0; i < 2; i++) {
        const int r0 = mt * 128 + wm * 32 + i * 16 + g;
        const int r1 = r0 + 8;
        const float sc0 = comp[r0 * 8 + zb];
        const float sc1 = comp[r1 * 8 + zb];
        __half* Cr0 = C + (size_t)r0 * 6144;
        __half* Cr1 = C + (size_t)r1 * 6144;
#pragma unroll
        for (int j = 0; j < 8; j++) {
            const int c = wn * 64 + j * 8 + 2 * t;
            *(__half2*)(Cr0 + c) =
                __floats2half2_rn(acc[i][j][0] * sc0, acc[i][j][1] * sc0);
            *(__half2*)(Cr1 + c) =
                __floats2half2_rn(acc[i][j][2] * sc1, acc[i][j][3] * sc1);
        }
    }
}

// ============================================================
// fp16 final GEMM: ldmatrix A-frags, single sync per chunk
// ============================================================
#define FA_W 1280
#define FB_W 2176
#define FSTG_W (FA_W + FB_W)
#define SMEM_F16 (3 * FSTG_W * 4)  // 41472

__global__ __launch_bounds__(256, 2)
void fin16_kernel(const __half* __restrict__ Oh,
                  const uint32_t* __restrict__ WF,
                  float* __restrict__ out) {
    extern __shared__ __align__(16) uint32_t smw[];
    const uint32_t sbase = smem_u32(smw);

    const int tid  = threadIdx.x;
    const int wid  = tid >> 5;
    const int lane = tid & 31;
    const int wm   = wid & 1;
    const int wn   = wid >> 1;
    const int g    = lane >> 2;
    const int t    = lane & 3;

    const int mt = blockIdx.x;
    const int zb = blockIdx.z;

    const uint32_t* Wh = WF + (size_t)zb * 49152;
    const __half* Ah = Oh + (size_t)(mt * 64) * 6144 + zb * 768;
    float* C = out + (size_t)zb * 128;

    const uint32_t a_lm = (uint32_t)((wm * 32 + (lane & 15)) * 80 +
                                     (lane >> 4) * 16);

    float acc[2][4][4];
#pragma unroll
    for (int i = 0; i < 2; i++)
#pragma unroll
        for (int j = 0; j < 4; j++)
#pragma unroll
            for (int c = 0; c < 4; c++) acc[i][j][c] = 0.f;

    auto issue_chunk = [&](int kc) {
        const int st = kc % 3;
        const uint32_t ad = sbase + (uint32_t)(st * FSTG_W) * 4;
        const uint32_t bd = ad + FA_W * 4;
        {
            int r = tid >> 2, c16 = tid & 3;
            cp16(ad + (uint32_t)(r * 20 + c16 * 4) * 4,
                 Ah + (size_t)r * 6144 + kc * 32 + c16 * 8);
        }
#pragma unroll
        for (int p = 0; p < 2; p++) {
            int idx = p * 256 + tid;
            int kpl = idx >> 5, c = idx & 31;
            cp16(bd + (uint32_t)(kpl * 136 + c * 4) * 4,
                 Wh + (size_t)(kc * 16 + kpl) * 128 + c * 4);
        }
    };

    issue_chunk(0);
    CP_COMMIT();
    issue_chunk(1);
    CP_COMMIT();

    for (int kc = 0; kc < 24; kc++) {
        if (kc + 1 < 24) { CP_WAIT(1); } else { CP_WAIT(0); }
        __syncthreads();
        if (kc + 2 < 24) { issue_chunk(kc + 2); CP_COMMIT(); }

        const uint32_t* bw = smw + (kc % 3) * FSTG_W + FA_W;
        const uint32_t a_stage = sbase + (uint32_t)((kc % 3) * FSTG_W) * 4 + a_lm;
#pragma unroll
        for (int ks = 0; ks < 2; ks++) {
            uint32_t af[2][4];
#pragma unroll
            for (int i = 0; i < 2; i++)
                ldm_x4(af[i], a_stage + i * 16 * 80 + ks * 32);
            uint32_t bf[4][2];
#pragma unroll
            for (int j = 0; j < 4; j++) {
                const int c = wn * 32 + j * 8 + g;
                bf[j][0] = bw[(ks * 8 + t)     * 136 + c];
                bf[j][1] = bw[(ks * 8 + 4 + t) * 136 + c];
            }
#pragma unroll
            for (int i = 0; i < 2; i++)
#pragma unroll
                for (int j = 0; j < 4; j++)
                    mma_f16(acc[i][j], af[i], bf[j]);
        }
    }

#pragma unroll
    for (int i = 0; i < 2; i++) {
        const int r0 = mt * 64 + wm * 32 + i * 16 + g;
        const int r1 = r0 + 8;
        float* Cr0 = C + (size_t)r0 * 1024;
        float* Cr1 = C + (size_t)r1 * 1024;
#pragma unroll
        for (int j = 0; j < 4; j++) {
            const int c = wn * 32 + j * 8 + 2 * t;
            *(float2*)(Cr0 + c) = make_float2(acc[i][j][0], acc[i][j][1]);
            *(float2*)(Cr1 + c) = make_float2(acc[i][j][2], acc[i][j][3]);
        }
    }
}

// ============================================================
// Kernel C: register/shuffle block-attention; fp16 output
// ============================================================
__global__ __launch_bounds__(384, 2)
void attn_kernel(float* __restrict__ out) {
    __shared__ float ss[12 * 64];

    const int t    = blockIdx.x;
    const int tid  = threadIdx.x;
    const int w    = tid >> 5;
    const int lane = tid & 31;
    const int n    = lane >> 2;
    const int p    = lane & 3;

    const size_t base = (size_t)t * 6144 + (size_t)n * 768 + w * 64 + p * 16;

    uint4 qa = *(const uint4*)(g_q + base);
    uint4 qb = *(const uint4*)(g_q + base + 8);
    uint4 ka = *(const uint4*)(g_k + base);
    uint4 kb = *(const uint4*)(g_k + base + 8);
    uint4 va = *(const uint4*)(g_v + base);
    uint4 vb = *(const uint4*)(g_v + base + 8);

    uint32_t kh[8] = {ka.x, ka.y, ka.z, ka.w, kb.x, kb.y, kb.z, kb.w};
    uint32_t vh[8] = {va.x, va.y, va.z, va.w, vb.x, vb.y, vb.z, vb.w};

    float qf[16];
    {
        const uint32_t qh[8] = {qa.x, qa.y, qa.z, qa.w, qb.x, qb.y, qb.z, qb.w};
#pragma unroll
        for (int r = 0; r < 8; r++) {
            float2 f = __half22float2(*(const __half2*)&qh[r]);
            qf[2 * r]     = f.x;
            qf[2 * r + 1] = f.y;
        }
    }

    float sc[8];
#pragma unroll
    for (int m = 0; m < 8; m++) {
        const int src = m * 4 + p;
        float a = 0.f;
#pragma unroll
        for (int r = 0; r < 8; r++) {
            uint32_t kk = __shfl_sync(0xffffffffu, kh[r], src);
            float2 f = __half22float2(*(const __half2*)&kk);
            a = fmaf(qf[2 * r], f.x, a);
            a = fmaf(qf[2 * r + 1], f.y, a);
        }
        sc[m] = a;
    }
#pragma unroll
    for (int o = 1; o <= 2; o <<= 1)
#pragma unroll
        for (int m = 0; m < 8; m++)
            sc[m] += __shfl_xor_sync(0xffffffffu, sc[m], o);
#pragma unroll
    for (int m = 0; m < 8; m++) sc[m] *= 0.125f;   // hd^-0.5

    float mx = sc[0];
#pragma unroll
    for (int m = 1; m < 8; m++) mx = fmaxf(mx, sc[m]);
    float den = 0.f;
#pragma unroll
    for (int m = 0; m < 8; m++) { sc[m] = __expf(sc[m] - mx); den += sc[m]; }
    const float inv = 1.0f / den;
#pragma unroll
    for (int m = 0; m < 8; m++) sc[m] *= inv;

    if (p == 0) {
#pragma unroll
        for (int m = 0; m < 8; m++) ss[w * 64 + n * 8 + m] = sc[m];
    }

    float of[16];
#pragma unroll
    for (int r = 0; r < 16; r++) of[r] = 0.f;
#pragma unroll
    for (int m = 0; m < 8; m++) {
        const int src = m * 4 + p;
        const float a = sc[m];
#pragma unroll
        for (int r = 0; r < 8; r++) {
            uint32_t vv = __shfl_sync(0xffffffffu, vh[r], src);
            float2 f = __half22float2(*(const __half2*)&vv);
            of[2 * r]     = fmaf(a, f.x, of[2 * r]);
            of[2 * r + 1] = fmaf(a, f.y, of[2 * r + 1]);
        }
    }
    __half2 oh[8];
#pragma unroll
    for (int r = 0; r < 8; r++)
        oh[r] = __floats2half2_rn(of[2 * r], of[2 * r + 1]);
    __half* dst = g_oh + base;
    *(uint4*)dst       = *(uint4*)&oh[0];
    *(uint4*)(dst + 8) = *(uint4*)&oh[4];

    __syncthreads();
    if (tid < 64) {
        float sum = 0.f;
#pragma unroll
        for (int h = 0; h < 12; h++) sum += ss[h * 64 + tid];
        out[4194304 + (size_t)t * 64 + tid] = sum * (1.0f / 12.0f);
    }
}

// ============================================================
// launch
// ============================================================
extern "C" void kernel_launch(void* const* d_in, const int* in_sizes, int n_in,
                              void* d_out, int out_size) {
    const float* x  = (const float*)d_in[0];
    const float* wc = (const float*)d_in[1];
    const float* wq = (const float*)d_in[2];
    const float* wk = (const float*)d_in[3];
    const float* wv = (const float*)d_in[4];
    const float* wf = (const float*)d_in[5];
    float* out = (float*)d_out;

    __half *gq, *gk, *gv, *goh, *gxh;
    __half2 *gwqh, *gwkh, *gwvh, *gwfh;
    float *gc;
    cudaGetSymbolAddress((void**)&gq, g_q);
    cudaGetSymbolAddress((void**)&gk, g_k);
    cudaGetSymbolAddress((void**)&gv, g_v);
    cudaGetSymbolAddress((void**)&goh, g_oh);
    cudaGetSymbolAddress((void**)&gc, g_comp);
    cudaGetSymbolAddress((void**)&gxh, g_xh);
    cudaGetSymbolAddress((void**)&gwqh, g_wqh);
    cudaGetSymbolAddress((void**)&gwkh, g_wkh);
    cudaGetSymbolAddress((void**)&gwvh, g_wvh);
    cudaGetSymbolAddress((void**)&gwfh, g_wfh);

    cudaFuncSetAttribute(qkv16_kernel,
                         cudaFuncAttributeMaxDynamicSharedMemorySize, SMEM_Q16);
    cudaFuncSetAttribute(fin16_kernel,
                         cudaFuncAttributeMaxDynamicSharedMemorySize, SMEM_F16);

    // fused prep (x fp16 + weight packs) + gating, one launch
    prep_kernel<<<TOTAL_BLKS, 256>>>(x, wq, wk, wv, wf, wc);

    // B: fp16 QKV GEMMs. 18 = 3 mats x 6 col-tiles of 128.
    dim3 gB(32, 18, 8);
    qkv16_kernel<<<gB, 256, SMEM_Q16>>>(
        gxh, (const uint32_t*)gwqh, (const uint32_t*)gwkh,
        (const uint32_t*)gwvh, gq, gk, gv, gc);

    // C: register/shuffle attention + score_mean (fp16 out)
    attn_kernel<<<TOK, 384>>>(out);

    // D: fp16 final GEMM. grid (64 m-tiles, 1, 8 blocks).
    dim3 gD(64, 1, 8);
    fin16_kernel<<<gD, 256, SMEM_F16>>>(goh, (const uint32_t*)gwfh, out);
}